// round 1
// baseline (speedup 1.0000x reference)
#include <cuda_runtime.h>
#include <math.h>

// Problem constants
#define E_DIM 1024
#define H_NUM 16
#define D_HEAD 64
#define B_SZ 2
#define L_SEQ 2048
#define S_SEQ 2048
#define M_ROWS (B_SZ * L_SEQ)   // 4096 (== B*S as well)

// ---------------- scratch (device globals; no allocations allowed) -----------
__device__ float g_Q[B_SZ * L_SEQ * E_DIM];
__device__ float g_K[B_SZ * S_SEQ * E_DIM];
__device__ float g_V[B_SZ * S_SEQ * E_DIM];
__device__ float g_AO[B_SZ * L_SEQ * E_DIM];

// ---------------- SGEMM: C[M,1024] = A[M,1024] @ W[1024,1024] + bias ---------
// 128x128 block tile, BK=16, 256 threads, 8x8 microtile (2x4 split rows/cols).
__global__ __launch_bounds__(256) void sgemm_bias_kernel(
    const float* __restrict__ A, const float* __restrict__ W,
    const float* __restrict__ bias, float* __restrict__ C) {
    __shared__ float As[16][132];   // transposed: As[k][m], padded
    __shared__ float Ws[16][128];   // Ws[k][n]

    const int tid = threadIdx.x;
    const int tx = tid & 15;        // 0..15 (col group)
    const int ty = tid >> 4;        // 0..15 (row group)
    const int m0 = blockIdx.y * 128;
    const int n0 = blockIdx.x * 128;

    float acc[8][8] = {};

    for (int k0 = 0; k0 < 1024; k0 += 16) {
        // Load A tile 128x16 (transposed into As)
#pragma unroll
        for (int t = 0; t < 2; t++) {
            int id = tid + t * 256;            // 0..511
            int row = id >> 2;                 // 0..127
            int kc = (id & 3) << 2;            // 0,4,8,12
            float4 a = *(const float4*)(A + (size_t)(m0 + row) * 1024 + k0 + kc);
            As[kc + 0][row] = a.x;
            As[kc + 1][row] = a.y;
            As[kc + 2][row] = a.z;
            As[kc + 3][row] = a.w;
        }
        // Load W tile 16x128
#pragma unroll
        for (int t = 0; t < 2; t++) {
            int id = tid + t * 256;            // 0..511
            int row = id >> 5;                 // 0..15
            int col = (id & 31) << 2;          // 0..124
            *(float4*)&Ws[row][col] =
                *(const float4*)(W + (size_t)(k0 + row) * 1024 + n0 + col);
        }
        __syncthreads();

#pragma unroll
        for (int kk = 0; kk < 16; kk++) {
            float ar[8], br[8];
            *(float4*)&ar[0] = *(const float4*)&As[kk][ty * 4];
            *(float4*)&ar[4] = *(const float4*)&As[kk][64 + ty * 4];
            *(float4*)&br[0] = *(const float4*)&Ws[kk][tx * 4];
            *(float4*)&br[4] = *(const float4*)&Ws[kk][64 + tx * 4];
#pragma unroll
            for (int i = 0; i < 8; i++)
#pragma unroll
                for (int j = 0; j < 8; j++)
                    acc[i][j] = fmaf(ar[i], br[j], acc[i][j]);
        }
        __syncthreads();
    }

    // Epilogue: add bias, store
#pragma unroll
    for (int rh = 0; rh < 2; rh++) {
#pragma unroll
        for (int r = 0; r < 4; r++) {
            int m = m0 + rh * 64 + ty * 4 + r;
#pragma unroll
            for (int ch = 0; ch < 2; ch++) {
                int n = n0 + ch * 64 + tx * 4;
                float4 bv = *(const float4*)&bias[n];
                float4 o;
                o.x = acc[rh * 4 + r][ch * 4 + 0] + bv.x;
                o.y = acc[rh * 4 + r][ch * 4 + 1] + bv.y;
                o.z = acc[rh * 4 + r][ch * 4 + 2] + bv.z;
                o.w = acc[rh * 4 + r][ch * 4 + 3] + bv.w;
                *(float4*)(C + (size_t)m * 1024 + n) = o;
            }
        }
    }
}

// ---------------- Flash attention ------------------------------------------
// Grid: (L/64, B*H). Block 256 threads. BR=BC=64, D=64.
// smem: Qs[d][i], Ks[d][j], Vs[j][d], Sc[i][j], all pitch 68.
#define SPITCH 68
#define ATTN_SMEM (4 * 64 * SPITCH * 4)

extern __shared__ float smem_att[];

__global__ __launch_bounds__(256) void attn_kernel(
    const float* __restrict__ Q, const float* __restrict__ K,
    const float* __restrict__ V, float* __restrict__ O) {
    float* Qs = smem_att;                 // [64][68]  Qs[d][i], pre-scaled
    float* Ks = Qs + 64 * SPITCH;         // [64][68]  Ks[d][j]
    float* Vs = Ks + 64 * SPITCH;         // [64][68]  Vs[j][d]
    float* Sc = Vs + 64 * SPITCH;         // [64][68]  Sc[i][j]
    __shared__ float sm[64], sl[64], sa[64];

    const int tid = threadIdx.x;
    const int tx = tid & 15;              // col group (j or d)
    const int ty = tid >> 4;              // row group (i)
    const int bh = blockIdx.y;
    const int b = bh >> 4;
    const int h = bh & 15;
    const int q0 = blockIdx.x * 64;

    const float* Qg = Q + ((size_t)(b * L_SEQ + q0)) * E_DIM + h * D_HEAD;
    const float* Kg0 = K + ((size_t)b * S_SEQ) * E_DIM + h * D_HEAD;
    const float* Vg0 = V + ((size_t)b * S_SEQ) * E_DIM + h * D_HEAD;

    // Load Q transposed, pre-scaled by 1/sqrt(D)=0.125
#pragma unroll
    for (int e = 0; e < 16; e++) {
        int idx = tid + e * 256;
        int i = idx >> 6;
        int d = idx & 63;
        Qs[d * SPITCH + i] = Qg[(size_t)i * E_DIM + d] * 0.125f;
    }
    if (tid < 64) { sm[tid] = -1e30f; sl[tid] = 0.0f; }

    float oacc[4][4] = {};
    __syncthreads();

    for (int t = 0; t < S_SEQ / 64; t++) {
        const float* Kg = Kg0 + (size_t)t * 64 * E_DIM;
        const float* Vg = Vg0 + (size_t)t * 64 * E_DIM;
#pragma unroll
        for (int e = 0; e < 16; e++) {
            int idx = tid + e * 256;
            int j = idx >> 6;
            int d = idx & 63;
            float kv = Kg[(size_t)j * E_DIM + d];
            float vv = Vg[(size_t)j * E_DIM + d];
            Ks[d * SPITCH + j] = kv;
            Vs[j * SPITCH + d] = vv;
        }
        __syncthreads();

        // ---- scores: Sc[i][j] = sum_d Qs[d][i] * Ks[d][j]
        {
            float acc[4][4] = {};
#pragma unroll 8
            for (int d = 0; d < 64; d++) {
                float4 q = *(const float4*)&Qs[d * SPITCH + ty * 4];
                float4 k = *(const float4*)&Ks[d * SPITCH + tx * 4];
                float qa[4] = {q.x, q.y, q.z, q.w};
                float ka[4] = {k.x, k.y, k.z, k.w};
#pragma unroll
                for (int r = 0; r < 4; r++)
#pragma unroll
                    for (int c = 0; c < 4; c++)
                        acc[r][c] = fmaf(qa[r], ka[c], acc[r][c]);
            }
#pragma unroll
            for (int r = 0; r < 4; r++) {
                float4 o = make_float4(acc[r][0], acc[r][1], acc[r][2], acc[r][3]);
                *(float4*)&Sc[(ty * 4 + r) * SPITCH + tx * 4] = o;
            }
        }
        __syncthreads();

        // ---- online softmax (4 threads per row, 16 cols each)
        {
            int row = tid >> 2;
            int seg = tid & 3;
            float* p = &Sc[row * SPITCH + seg * 16];
            float mx = -1e30f;
#pragma unroll
            for (int c = 0; c < 16; c++) mx = fmaxf(mx, p[c]);
            mx = fmaxf(mx, __shfl_xor_sync(0xffffffffu, mx, 1));
            mx = fmaxf(mx, __shfl_xor_sync(0xffffffffu, mx, 2));
            float m_old = sm[row];
            float m_new = fmaxf(m_old, mx);
            float sum = 0.0f;
#pragma unroll
            for (int c = 0; c < 16; c++) {
                float pv = __expf(p[c] - m_new);
                p[c] = pv;
                sum += pv;
            }
            sum += __shfl_xor_sync(0xffffffffu, sum, 1);
            sum += __shfl_xor_sync(0xffffffffu, sum, 2);
            if (seg == 0) {
                float a = __expf(m_old - m_new);
                sa[row] = a;
                sl[row] = sl[row] * a + sum;
                sm[row] = m_new;
            }
        }
        __syncthreads();

        // ---- rescale O and accumulate P @ V
        {
#pragma unroll
            for (int r = 0; r < 4; r++) {
                float a = sa[ty * 4 + r];
#pragma unroll
                for (int c = 0; c < 4; c++) oacc[r][c] *= a;
            }
#pragma unroll 4
            for (int j4 = 0; j4 < 64; j4 += 4) {
                float4 pr[4];
#pragma unroll
                for (int r = 0; r < 4; r++)
                    pr[r] = *(const float4*)&Sc[(ty * 4 + r) * SPITCH + j4];
#pragma unroll
                for (int jj = 0; jj < 4; jj++) {
                    float4 v = *(const float4*)&Vs[(j4 + jj) * SPITCH + tx * 4];
                    float va[4] = {v.x, v.y, v.z, v.w};
#pragma unroll
                    for (int r = 0; r < 4; r++) {
                        float ps = ((const float*)&pr[r])[jj];
#pragma unroll
                        for (int c = 0; c < 4; c++)
                            oacc[r][c] = fmaf(ps, va[c], oacc[r][c]);
                    }
                }
            }
        }
        __syncthreads();
    }

    // ---- finalize: divide by l, write out in [B,L,E] layout
    {
        float* Og = O + ((size_t)(b * L_SEQ + q0)) * E_DIM + h * D_HEAD;
#pragma unroll
        for (int r = 0; r < 4; r++) {
            int i = ty * 4 + r;
            float inv = 1.0f / sl[i];
            float4 o = make_float4(oacc[r][0] * inv, oacc[r][1] * inv,
                                   oacc[r][2] * inv, oacc[r][3] * inv);
            *(float4*)&Og[(size_t)i * E_DIM + tx * 4] = o;
        }
    }
}

// ---------------- launch -----------------------------------------------------
extern "C" void kernel_launch(void* const* d_in, const int* in_sizes, int n_in,
                              void* d_out, int out_size) {
    (void)in_sizes; (void)n_in; (void)out_size;
    const float* x   = (const float*)d_in[0];
    const float* ctx = (const float*)d_in[1];
    const float* Wq  = (const float*)d_in[2];
    const float* bq  = (const float*)d_in[3];
    const float* Wk  = (const float*)d_in[4];
    const float* bk  = (const float*)d_in[5];
    const float* Wv  = (const float*)d_in[6];
    const float* bv  = (const float*)d_in[7];
    const float* Wp  = (const float*)d_in[8];
    const float* bp  = (const float*)d_in[9];
    float* out = (float*)d_out;

    float *pQ, *pK, *pV, *pAO;
    cudaGetSymbolAddress((void**)&pQ, g_Q);
    cudaGetSymbolAddress((void**)&pK, g_K);
    cudaGetSymbolAddress((void**)&pV, g_V);
    cudaGetSymbolAddress((void**)&pAO, g_AO);

    cudaFuncSetAttribute(attn_kernel, cudaFuncAttributeMaxDynamicSharedMemorySize,
                         ATTN_SMEM);

    dim3 gGemm(1024 / 128, M_ROWS / 128);   // (8, 32)
    sgemm_bias_kernel<<<gGemm, 256>>>(x,   Wq, bq, pQ);
    sgemm_bias_kernel<<<gGemm, 256>>>(ctx, Wk, bk, pK);
    sgemm_bias_kernel<<<gGemm, 256>>>(ctx, Wv, bv, pV);

    dim3 gAttn(L_SEQ / 64, B_SZ * H_NUM);   // (32, 32)
    attn_kernel<<<gAttn, 256, ATTN_SMEM>>>(pQ, pK, pV, pAO);

    sgemm_bias_kernel<<<gGemm, 256>>>(pAO, Wp, bp, out);
}

// round 6
// speedup vs baseline: 1.3928x; 1.3928x over previous
#include <cuda_runtime.h>
#include <math.h>
#include <stdint.h>

// Problem constants
#define E_DIM 1024
#define H_NUM 16
#define D_HEAD 64
#define B_SZ 2
#define L_SEQ 2048
#define S_SEQ 2048
#define M_ROWS (B_SZ * L_SEQ)   // 4096

// ---------------- scratch (device globals; no allocations allowed) -----------
__device__ float g_Q[B_SZ * L_SEQ * E_DIM];
__device__ float g_K[B_SZ * S_SEQ * E_DIM];
__device__ float g_V[B_SZ * S_SEQ * E_DIM];
__device__ float g_AO[B_SZ * L_SEQ * E_DIM];
__device__ float g_Wt[4][E_DIM * E_DIM];   // transposed weights [N][K]

// ---------------- helpers ----------------------------------------------------
__device__ __forceinline__ uint32_t f2tf32(float x) {
    uint32_t r;
    asm("cvt.rna.tf32.f32 %0, %1;" : "=r"(r) : "f"(x));
    return r;
}

__device__ __forceinline__ void mma_tf32(float c[4], const uint32_t a[4],
                                         const uint32_t b[2]) {
    asm volatile(
        "mma.sync.aligned.m16n8k8.row.col.f32.tf32.tf32.f32 "
        "{%0,%1,%2,%3}, {%4,%5,%6,%7}, {%8,%9}, {%0,%1,%2,%3};"
        : "+f"(c[0]), "+f"(c[1]), "+f"(c[2]), "+f"(c[3])
        : "r"(a[0]), "r"(a[1]), "r"(a[2]), "r"(a[3]), "r"(b[0]), "r"(b[1]));
}

// ---------------- weight transpose: Wt[n][k] = W[k][n] -----------------------
__global__ __launch_bounds__(256) void transpose_kernel(
    const float* __restrict__ W, float* __restrict__ Wt) {
    __shared__ float t[32][33];
    int x = blockIdx.x * 32 + threadIdx.x;
    int y0 = blockIdx.y * 32 + threadIdx.y;
#pragma unroll
    for (int j = 0; j < 32; j += 8)
        t[threadIdx.y + j][threadIdx.x] = W[(size_t)(y0 + j) * E_DIM + x];
    __syncthreads();
    int xo = blockIdx.y * 32 + threadIdx.x;
    int yo = blockIdx.x * 32 + threadIdx.y;
#pragma unroll
    for (int j = 0; j < 32; j += 8)
        Wt[(size_t)(yo + j) * E_DIM + xo] = t[threadIdx.x][threadIdx.y + j];
}

// ---------------- mma.sync tf32 GEMM: C[M,1024] = A @ Bt^T + bias ------------
// A row-major [M,K], Bt row-major [N,K]. CTA 128x128, BK=32, 8 warps (2x4),
// warp tile 64x32 = 4x4 m16n8k8 fragments. Double-buffered smem, pitch 36.
#define SPAD 36
#define GEMM_SMEM (4 * 128 * SPAD * 4)   // 2 bufs x (A+B) x 128 x 36 floats

__global__ __launch_bounds__(256) void gemm_mma(
    const float* __restrict__ A, const float* __restrict__ Bt,
    const float* __restrict__ bias, float* __restrict__ C) {
    extern __shared__ float gsm[];
    float* sA = gsm;                     // [2][128*SPAD]
    float* sB = gsm + 2 * 128 * SPAD;    // [2][128*SPAD]

    const int tid = threadIdx.x;
    const int lane = tid & 31;
    const int wid = tid >> 5;
    const int g = lane >> 2;      // 0..7
    const int tg = lane & 3;      // 0..3
    const int wm = wid & 1;       // warp row  (64 rows each)
    const int wn = wid >> 1;      // warp col  (32 cols each)
    const int m0 = blockIdx.y * 128;
    const int n0 = blockIdx.x * 128;

    const int lrow = tid >> 3;         // 0..31 (+ j*32)
    const int lc4 = (tid & 7) * 4;     // k-col within chunk

    float acc[4][4][4] = {};
    float4 ra[4], rb[4];

    const float* Ag = A + (size_t)(m0 + lrow) * 1024 + lc4;
    const float* Bg = Bt + (size_t)(n0 + lrow) * 1024 + lc4;

    // prefetch chunk 0
#pragma unroll
    for (int j = 0; j < 4; j++) {
        ra[j] = *(const float4*)(Ag + (size_t)j * 32 * 1024);
        rb[j] = *(const float4*)(Bg + (size_t)j * 32 * 1024);
    }

    for (int it = 0; it < 32; ++it) {
        // store prefetched chunk (tf32-rounded) into buffer it&1
        {
            float* dA = sA + (it & 1) * 128 * SPAD;
            float* dB = sB + (it & 1) * 128 * SPAD;
#pragma unroll
            for (int j = 0; j < 4; j++) {
                uint4 ta = make_uint4(f2tf32(ra[j].x), f2tf32(ra[j].y),
                                      f2tf32(ra[j].z), f2tf32(ra[j].w));
                *(uint4*)&dA[(lrow + j * 32) * SPAD + lc4] = ta;
                uint4 tb = make_uint4(f2tf32(rb[j].x), f2tf32(rb[j].y),
                                      f2tf32(rb[j].z), f2tf32(rb[j].w));
                *(uint4*)&dB[(lrow + j * 32) * SPAD + lc4] = tb;
            }
        }
        __syncthreads();

        // prefetch next chunk while computing
        if (it + 1 < 32) {
            const float* An = Ag + (size_t)(it + 1) * 32;
            const float* Bn = Bg + (size_t)(it + 1) * 32;
#pragma unroll
            for (int j = 0; j < 4; j++) {
                ra[j] = *(const float4*)(An + (size_t)j * 32 * 1024);
                rb[j] = *(const float4*)(Bn + (size_t)j * 32 * 1024);
            }
        }

        // compute from buffer it&1
        {
            const uint32_t* cA =
                (const uint32_t*)(sA + (it & 1) * 128 * SPAD);
            const uint32_t* cB =
                (const uint32_t*)(sB + (it & 1) * 128 * SPAD);
#pragma unroll
            for (int ks = 0; ks < 4; ks++) {
                const int kb = ks * 8;
                uint32_t af[4][4];
#pragma unroll
                for (int mt = 0; mt < 4; mt++) {
                    const int r = wm * 64 + mt * 16 + g;
                    af[mt][0] = cA[r * SPAD + kb + tg];
                    af[mt][1] = cA[(r + 8) * SPAD + kb + tg];
                    af[mt][2] = cA[r * SPAD + kb + tg + 4];
                    af[mt][3] = cA[(r + 8) * SPAD + kb + tg + 4];
                }
                uint32_t bf[4][2];
#pragma unroll
                for (int nt = 0; nt < 4; nt++) {
                    const int c = wn * 32 + nt * 8 + g;
                    bf[nt][0] = cB[c * SPAD + kb + tg];
                    bf[nt][1] = cB[c * SPAD + kb + tg + 4];
                }
#pragma unroll
                for (int mt = 0; mt < 4; mt++)
#pragma unroll
                    for (int nt = 0; nt < 4; nt++)
                        mma_tf32(acc[mt][nt], af[mt], bf[nt]);
            }
        }
        __syncthreads();
    }

    // Epilogue: bias + store (float2 per fragment half-row)
#pragma unroll
    for (int mt = 0; mt < 4; mt++) {
        const int row = m0 + wm * 64 + mt * 16 + g;
#pragma unroll
        for (int nt = 0; nt < 4; nt++) {
            const int col = n0 + wn * 32 + nt * 8 + tg * 2;
            const float2 bv = *(const float2*)&bias[col];
            float2 o0, o1;
            o0.x = acc[mt][nt][0] + bv.x;
            o0.y = acc[mt][nt][1] + bv.y;
            o1.x = acc[mt][nt][2] + bv.x;
            o1.y = acc[mt][nt][3] + bv.y;
            *(float2*)(C + (size_t)row * 1024 + col) = o0;
            *(float2*)(C + (size_t)(row + 8) * 1024 + col) = o1;
        }
    }
}

// ---------------- Flash attention (unchanged from round 1) ------------------
#define SPITCH 68
#define ATTN_SMEM (4 * 64 * SPITCH * 4)

extern __shared__ float smem_att[];

__global__ __launch_bounds__(256) void attn_kernel(
    const float* __restrict__ Q, const float* __restrict__ K,
    const float* __restrict__ V, float* __restrict__ O) {
    float* Qs = smem_att;
    float* Ks = Qs + 64 * SPITCH;
    float* Vs = Ks + 64 * SPITCH;
    float* Sc = Vs + 64 * SPITCH;
    __shared__ float sm[64], sl[64], sa[64];

    const int tid = threadIdx.x;
    const int tx = tid & 15;
    const int ty = tid >> 4;
    const int bh = blockIdx.y;
    const int b = bh >> 4;
    const int h = bh & 15;
    const int q0 = blockIdx.x * 64;

    const float* Qg = Q + ((size_t)(b * L_SEQ + q0)) * E_DIM + h * D_HEAD;
    const float* Kg0 = K + ((size_t)b * S_SEQ) * E_DIM + h * D_HEAD;
    const float* Vg0 = V + ((size_t)b * S_SEQ) * E_DIM + h * D_HEAD;

#pragma unroll
    for (int e = 0; e < 16; e++) {
        int idx = tid + e * 256;
        int i = idx >> 6;
        int d = idx & 63;
        Qs[d * SPITCH + i] = Qg[(size_t)i * E_DIM + d] * 0.125f;
    }
    if (tid < 64) { sm[tid] = -1e30f; sl[tid] = 0.0f; }

    float oacc[4][4] = {};
    __syncthreads();

    for (int t = 0; t < S_SEQ / 64; t++) {
        const float* Kg = Kg0 + (size_t)t * 64 * E_DIM;
        const float* Vg = Vg0 + (size_t)t * 64 * E_DIM;
#pragma unroll
        for (int e = 0; e < 16; e++) {
            int idx = tid + e * 256;
            int j = idx >> 6;
            int d = idx & 63;
            Ks[d * SPITCH + j] = Kg[(size_t)j * E_DIM + d];
            Vs[j * SPITCH + d] = Vg[(size_t)j * E_DIM + d];
        }
        __syncthreads();

        {
            float acc[4][4] = {};
#pragma unroll 8
            for (int d = 0; d < 64; d++) {
                float4 q = *(const float4*)&Qs[d * SPITCH + ty * 4];
                float4 k = *(const float4*)&Ks[d * SPITCH + tx * 4];
                float qa[4] = {q.x, q.y, q.z, q.w};
                float ka[4] = {k.x, k.y, k.z, k.w};
#pragma unroll
                for (int r = 0; r < 4; r++)
#pragma unroll
                    for (int c = 0; c < 4; c++)
                        acc[r][c] = fmaf(qa[r], ka[c], acc[r][c]);
            }
#pragma unroll
            for (int r = 0; r < 4; r++) {
                float4 o = make_float4(acc[r][0], acc[r][1], acc[r][2], acc[r][3]);
                *(float4*)&Sc[(ty * 4 + r) * SPITCH + tx * 4] = o;
            }
        }
        __syncthreads();

        {
            int row = tid >> 2;
            int seg = tid & 3;
            float* p = &Sc[row * SPITCH + seg * 16];
            float mx = -1e30f;
#pragma unroll
            for (int c = 0; c < 16; c++) mx = fmaxf(mx, p[c]);
            mx = fmaxf(mx, __shfl_xor_sync(0xffffffffu, mx, 1));
            mx = fmaxf(mx, __shfl_xor_sync(0xffffffffu, mx, 2));
            float m_old = sm[row];
            float m_new = fmaxf(m_old, mx);
            float sum = 0.0f;
#pragma unroll
            for (int c = 0; c < 16; c++) {
                float pv = __expf(p[c] - m_new);
                p[c] = pv;
                sum += pv;
            }
            sum += __shfl_xor_sync(0xffffffffu, sum, 1);
            sum += __shfl_xor_sync(0xffffffffu, sum, 2);
            if (seg == 0) {
                float a = __expf(m_old - m_new);
                sa[row] = a;
                sl[row] = sl[row] * a + sum;
                sm[row] = m_new;
            }
        }
        __syncthreads();

        {
#pragma unroll
            for (int r = 0; r < 4; r++) {
                float a = sa[ty * 4 + r];
#pragma unroll
                for (int c = 0; c < 4; c++) oacc[r][c] *= a;
            }
#pragma unroll 4
            for (int j4 = 0; j4 < 64; j4 += 4) {
                float4 pr[4];
#pragma unroll
                for (int r = 0; r < 4; r++)
                    pr[r] = *(const float4*)&Sc[(ty * 4 + r) * SPITCH + j4];
#pragma unroll
                for (int jj = 0; jj < 4; jj++) {
                    float4 v = *(const float4*)&Vs[(j4 + jj) * SPITCH + tx * 4];
                    float va[4] = {v.x, v.y, v.z, v.w};
#pragma unroll
                    for (int r = 0; r < 4; r++) {
                        float ps = ((const float*)&pr[r])[jj];
#pragma unroll
                        for (int c = 0; c < 4; c++)
                            oacc[r][c] = fmaf(ps, va[c], oacc[r][c]);
                    }
                }
            }
        }
        __syncthreads();
    }

    {
        float* Og = O + ((size_t)(b * L_SEQ + q0)) * E_DIM + h * D_HEAD;
#pragma unroll
        for (int r = 0; r < 4; r++) {
            int i = ty * 4 + r;
            float inv = 1.0f / sl[i];
            float4 o = make_float4(oacc[r][0] * inv, oacc[r][1] * inv,
                                   oacc[r][2] * inv, oacc[r][3] * inv);
            *(float4*)&Og[(size_t)i * E_DIM + tx * 4] = o;
        }
    }
}

// ---------------- launch -----------------------------------------------------
extern "C" void kernel_launch(void* const* d_in, const int* in_sizes, int n_in,
                              void* d_out, int out_size) {
    (void)in_sizes; (void)n_in; (void)out_size;
    const float* x   = (const float*)d_in[0];
    const float* ctx = (const float*)d_in[1];
    const float* Wq  = (const float*)d_in[2];
    const float* bq  = (const float*)d_in[3];
    const float* Wk  = (const float*)d_in[4];
    const float* bk  = (const float*)d_in[5];
    const float* Wv  = (const float*)d_in[6];
    const float* bv  = (const float*)d_in[7];
    const float* Wp  = (const float*)d_in[8];
    const float* bp  = (const float*)d_in[9];
    float* out = (float*)d_out;

    float *pQ, *pK, *pV, *pAO, *pWt;
    cudaGetSymbolAddress((void**)&pQ, g_Q);
    cudaGetSymbolAddress((void**)&pK, g_K);
    cudaGetSymbolAddress((void**)&pV, g_V);
    cudaGetSymbolAddress((void**)&pAO, g_AO);
    cudaGetSymbolAddress((void**)&pWt, g_Wt);
    float* WtQ = pWt + 0 * (size_t)E_DIM * E_DIM;
    float* WtK = pWt + 1 * (size_t)E_DIM * E_DIM;
    float* WtV = pWt + 2 * (size_t)E_DIM * E_DIM;
    float* WtP = pWt + 3 * (size_t)E_DIM * E_DIM;

    cudaFuncSetAttribute(gemm_mma, cudaFuncAttributeMaxDynamicSharedMemorySize,
                         GEMM_SMEM);
    cudaFuncSetAttribute(attn_kernel, cudaFuncAttributeMaxDynamicSharedMemorySize,
                         ATTN_SMEM);

    dim3 tGrid(E_DIM / 32, E_DIM / 32);
    dim3 tBlk(32, 8);
    transpose_kernel<<<tGrid, tBlk>>>(Wq, WtQ);
    transpose_kernel<<<tGrid, tBlk>>>(Wk, WtK);
    transpose_kernel<<<tGrid, tBlk>>>(Wv, WtV);
    transpose_kernel<<<tGrid, tBlk>>>(Wp, WtP);

    dim3 gGemm(E_DIM / 128, M_ROWS / 128);   // (8, 32)
    gemm_mma<<<gGemm, 256, GEMM_SMEM>>>(x,   WtQ, bq, pQ);
    gemm_mma<<<gGemm, 256, GEMM_SMEM>>>(ctx, WtK, bk, pK);
    gemm_mma<<<gGemm, 256, GEMM_SMEM>>>(ctx, WtV, bv, pV);

    dim3 gAttn(L_SEQ / 64, B_SZ * H_NUM);    // (32, 32)
    attn_kernel<<<gAttn, 256, ATTN_SMEM>>>(pQ, pK, pV, pAO);

    gemm_mma<<<gGemm, 256, GEMM_SMEM>>>(pAO, WtP, bp, out);
}

// round 8
// speedup vs baseline: 2.1946x; 1.5757x over previous
#include <cuda_runtime.h>
#include <math.h>
#include <stdint.h>

// Problem constants
#define E_DIM 1024
#define H_NUM 16
#define D_HEAD 64
#define B_SZ 2
#define L_SEQ 2048
#define S_SEQ 2048
#define M_ROWS (B_SZ * L_SEQ)   // 4096

// ---------------- scratch (device globals; no allocations allowed) -----------
__device__ float g_Q[B_SZ * L_SEQ * E_DIM];
__device__ float g_K[B_SZ * S_SEQ * E_DIM];
__device__ float g_V[B_SZ * S_SEQ * E_DIM];
__device__ float g_AO[B_SZ * L_SEQ * E_DIM];
__device__ float g_Wt[4][E_DIM * E_DIM];   // transposed weights [N][K]

// ---------------- helpers ----------------------------------------------------
__device__ __forceinline__ uint32_t f2tf32(float x) {
    uint32_t r;
    asm("cvt.rna.tf32.f32 %0, %1;" : "=r"(r) : "f"(x));
    return r;
}

__device__ __forceinline__ void mma_tf32(float c[4], const uint32_t a[4],
                                         const uint32_t b[2]) {
    asm volatile(
        "mma.sync.aligned.m16n8k8.row.col.f32.tf32.tf32.f32 "
        "{%0,%1,%2,%3}, {%4,%5,%6,%7}, {%8,%9}, {%0,%1,%2,%3};"
        : "+f"(c[0]), "+f"(c[1]), "+f"(c[2]), "+f"(c[3])
        : "r"(a[0]), "r"(a[1]), "r"(a[2]), "r"(a[3]), "r"(b[0]), "r"(b[1]));
}

__device__ __forceinline__ void mma_bf16(float c[4], const uint32_t a[4],
                                         const uint32_t b[2]) {
    asm volatile(
        "mma.sync.aligned.m16n8k16.row.col.f32.bf16.bf16.f32 "
        "{%0,%1,%2,%3}, {%4,%5,%6,%7}, {%8,%9}, {%0,%1,%2,%3};"
        : "+f"(c[0]), "+f"(c[1]), "+f"(c[2]), "+f"(c[3])
        : "r"(a[0]), "r"(a[1]), "r"(a[2]), "r"(a[3]), "r"(b[0]), "r"(b[1]));
}

// bf16 split helpers: hi = truncate-to-bf16 (top 16 bits), lo = residual.
__device__ __forceinline__ float hi_part(float x) {
    return __uint_as_float(__float_as_uint(x) & 0xffff0000u);
}
// pack bf16(x0) into low half, bf16(x1) into high half (truncation)
__device__ __forceinline__ uint32_t pack_hi(float x0, float x1) {
    uint32_t u0 = __float_as_uint(x0), u1 = __float_as_uint(x1);
    return (u1 & 0xffff0000u) | (u0 >> 16);
}

// ---------------- weight transpose: Wt[n][k] = W[k][n] -----------------------
__global__ __launch_bounds__(256) void transpose_kernel(
    const float* __restrict__ W, float* __restrict__ Wt) {
    __shared__ float t[32][33];
    int x = blockIdx.x * 32 + threadIdx.x;
    int y0 = blockIdx.y * 32 + threadIdx.y;
#pragma unroll
    for (int j = 0; j < 32; j += 8)
        t[threadIdx.y + j][threadIdx.x] = W[(size_t)(y0 + j) * E_DIM + x];
    __syncthreads();
    int xo = blockIdx.y * 32 + threadIdx.x;
    int yo = blockIdx.x * 32 + threadIdx.y;
#pragma unroll
    for (int j = 0; j < 32; j += 8)
        Wt[(size_t)(yo + j) * E_DIM + xo] = t[threadIdx.x][threadIdx.y + j];
}

// ---------------- mma.sync tf32 GEMM (unchanged from round 6) ----------------
#define SPAD 36
#define GEMM_SMEM (4 * 128 * SPAD * 4)

__global__ __launch_bounds__(256) void gemm_mma(
    const float* __restrict__ A, const float* __restrict__ Bt,
    const float* __restrict__ bias, float* __restrict__ C) {
    extern __shared__ float gsm[];
    float* sA = gsm;
    float* sB = gsm + 2 * 128 * SPAD;

    const int tid = threadIdx.x;
    const int lane = tid & 31;
    const int wid = tid >> 5;
    const int g = lane >> 2;
    const int tg = lane & 3;
    const int wm = wid & 1;
    const int wn = wid >> 1;
    const int m0 = blockIdx.y * 128;
    const int n0 = blockIdx.x * 128;

    const int lrow = tid >> 3;
    const int lc4 = (tid & 7) * 4;

    float acc[4][4][4] = {};
    float4 ra[4], rb[4];

    const float* Ag = A + (size_t)(m0 + lrow) * 1024 + lc4;
    const float* Bg = Bt + (size_t)(n0 + lrow) * 1024 + lc4;

#pragma unroll
    for (int j = 0; j < 4; j++) {
        ra[j] = *(const float4*)(Ag + (size_t)j * 32 * 1024);
        rb[j] = *(const float4*)(Bg + (size_t)j * 32 * 1024);
    }

    for (int it = 0; it < 32; ++it) {
        {
            float* dA = sA + (it & 1) * 128 * SPAD;
            float* dB = sB + (it & 1) * 128 * SPAD;
#pragma unroll
            for (int j = 0; j < 4; j++) {
                uint4 ta = make_uint4(f2tf32(ra[j].x), f2tf32(ra[j].y),
                                      f2tf32(ra[j].z), f2tf32(ra[j].w));
                *(uint4*)&dA[(lrow + j * 32) * SPAD + lc4] = ta;
                uint4 tb = make_uint4(f2tf32(rb[j].x), f2tf32(rb[j].y),
                                      f2tf32(rb[j].z), f2tf32(rb[j].w));
                *(uint4*)&dB[(lrow + j * 32) * SPAD + lc4] = tb;
            }
        }
        __syncthreads();

        if (it + 1 < 32) {
            const float* An = Ag + (size_t)(it + 1) * 32;
            const float* Bn = Bg + (size_t)(it + 1) * 32;
#pragma unroll
            for (int j = 0; j < 4; j++) {
                ra[j] = *(const float4*)(An + (size_t)j * 32 * 1024);
                rb[j] = *(const float4*)(Bn + (size_t)j * 32 * 1024);
            }
        }

        {
            const uint32_t* cA = (const uint32_t*)(sA + (it & 1) * 128 * SPAD);
            const uint32_t* cB = (const uint32_t*)(sB + (it & 1) * 128 * SPAD);
#pragma unroll
            for (int ks = 0; ks < 4; ks++) {
                const int kb = ks * 8;
                uint32_t af[4][4];
#pragma unroll
                for (int mt = 0; mt < 4; mt++) {
                    const int r = wm * 64 + mt * 16 + g;
                    af[mt][0] = cA[r * SPAD + kb + tg];
                    af[mt][1] = cA[(r + 8) * SPAD + kb + tg];
                    af[mt][2] = cA[r * SPAD + kb + tg + 4];
                    af[mt][3] = cA[(r + 8) * SPAD + kb + tg + 4];
                }
                uint32_t bf[4][2];
#pragma unroll
                for (int nt = 0; nt < 4; nt++) {
                    const int c = wn * 32 + nt * 8 + g;
                    bf[nt][0] = cB[c * SPAD + kb + tg];
                    bf[nt][1] = cB[c * SPAD + kb + tg + 4];
                }
#pragma unroll
                for (int mt = 0; mt < 4; mt++)
#pragma unroll
                    for (int nt = 0; nt < 4; nt++)
                        mma_tf32(acc[mt][nt], af[mt], bf[nt]);
            }
        }
        __syncthreads();
    }

#pragma unroll
    for (int mt = 0; mt < 4; mt++) {
        const int row = m0 + wm * 64 + mt * 16 + g;
#pragma unroll
        for (int nt = 0; nt < 4; nt++) {
            const int col = n0 + wn * 32 + nt * 8 + tg * 2;
            const float2 bv = *(const float2*)&bias[col];
            float2 o0, o1;
            o0.x = acc[mt][nt][0] + bv.x;
            o0.y = acc[mt][nt][1] + bv.y;
            o1.x = acc[mt][nt][2] + bv.x;
            o1.y = acc[mt][nt][3] + bv.y;
            *(float2*)(C + (size_t)row * 1024 + col) = o0;
            *(float2*)(C + (size_t)(row + 8) * 1024 + col) = o1;
        }
    }
}

// ---------------- Flash attention via mma.sync bf16 (3-MMA split) -----------
// CTA: 128 queries (BR), 64 keys per iter (BC), D=64, 8 warps (2 x 4).
// smem (u32 units): Qh/Ql [128][36], Kh/Kl [64][36], Vh/Vl [64][36] (V transp),
// Ph/Pl [128][36], S fp32 [128][68], sm/sl/sa [128].
#define AQH 0
#define AQL 4608
#define AKH 9216
#define AKL 11520
#define AVH 13824
#define AVL 16128
#define APH 18432
#define APL 23040
#define AS  27648
#define ASM 36352
#define ASL 36480
#define ASA 36608
#define ATTN_SMEM (36736 * 4)

__global__ __launch_bounds__(256) void attn_mma(
    const float* __restrict__ Q, const float* __restrict__ K,
    const float* __restrict__ V, float* __restrict__ O) {
    extern __shared__ uint32_t smu[];
    uint32_t* Qh = smu + AQH;
    uint32_t* Ql = smu + AQL;
    uint32_t* Kh = smu + AKH;
    uint32_t* Kl = smu + AKL;
    uint32_t* Vh = smu + AVH;
    uint32_t* Vl = smu + AVL;
    uint32_t* Ph = smu + APH;
    uint32_t* Pl = smu + APL;
    float* S   = (float*)(smu + AS);
    float* s_m = (float*)(smu + ASM);
    float* s_l = (float*)(smu + ASL);
    float* s_a = (float*)(smu + ASA);

    const int tid = threadIdx.x;
    const int lane = tid & 31;
    const int wid = tid >> 5;
    const int g = lane >> 2;
    const int tg = lane & 3;
    const int wm = wid & 1;       // 64-row half
    const int wn = wid >> 1;      // 16-col slice
    const int bh = blockIdx.y;
    const int b = bh >> 4;
    const int h = bh & 15;
    const int q0 = blockIdx.x * 128;

    const float* Qg = Q + (size_t)(b * L_SEQ + q0) * E_DIM + h * D_HEAD;
    const float* Kg0 = K + (size_t)b * S_SEQ * E_DIM + h * D_HEAD;
    const float* Vg0 = V + (size_t)b * S_SEQ * E_DIM + h * D_HEAD;

    // Load Q once: pre-scale by 1/8, split into bf16 hi/lo, pack pairs along d.
#pragma unroll
    for (int p = 0; p < 16; p++) {
        int idx = tid + p * 256;          // 0..4095
        int r = idx >> 5;                 // 0..127
        int dp = idx & 31;                // d-pair
        float2 q = *(const float2*)(Qg + (size_t)r * E_DIM + 2 * dp);
        float x0 = q.x * 0.125f, x1 = q.y * 0.125f;
        Qh[r * 36 + dp] = pack_hi(x0, x1);
        Ql[r * 36 + dp] = pack_hi(x0 - hi_part(x0), x1 - hi_part(x1));
    }
    if (tid < 128) { s_m[tid] = -1e30f; s_l[tid] = 0.0f; }

    float oacc[4][2][4] = {};

    for (int t = 0; t < S_SEQ / 64; ++t) {
        const float* Kg = Kg0 + (size_t)t * 64 * E_DIM;
        const float* Vg = Vg0 + (size_t)t * 64 * E_DIM;
        // K: [j][d] -> packed pairs along d
#pragma unroll
        for (int p = 0; p < 8; p++) {
            int idx = tid + p * 256;      // 0..2047
            int j = idx >> 5;             // 0..63
            int dp = idx & 31;
            float2 kv = *(const float2*)(Kg + (size_t)j * E_DIM + 2 * dp);
            Kh[j * 36 + dp] = pack_hi(kv.x, kv.y);
            Kl[j * 36 + dp] = pack_hi(kv.x - hi_part(kv.x), kv.y - hi_part(kv.y));
        }
        // V transposed: Vh[d][j-pair]
#pragma unroll
        for (int p = 0; p < 8; p++) {
            int idx = tid + p * 256;      // 0..2047
            int d = idx & 63;
            int jp = idx >> 6;            // 0..31
            float v0 = Vg[(size_t)(2 * jp) * E_DIM + d];
            float v1 = Vg[(size_t)(2 * jp + 1) * E_DIM + d];
            Vh[d * 36 + jp] = pack_hi(v0, v1);
            Vl[d * 36 + jp] = pack_hi(v0 - hi_part(v0), v1 - hi_part(v1));
        }
        __syncthreads();

        // ---- QK^T: S[128][64], 3 MMAs per tile (qh*kh + ql*kh + qh*kl)
        {
            float sc[4][2][4] = {};
#pragma unroll
            for (int ks = 0; ks < 4; ks++) {
                uint32_t ah[4][4], al[4][4];
#pragma unroll
                for (int mt = 0; mt < 4; mt++) {
                    int r0 = (wm * 64 + mt * 16 + g) * 36 + ks * 8 + tg;
                    ah[mt][0] = Qh[r0];       ah[mt][1] = Qh[r0 + 288];
                    ah[mt][2] = Qh[r0 + 4];   ah[mt][3] = Qh[r0 + 292];
                    al[mt][0] = Ql[r0];       al[mt][1] = Ql[r0 + 288];
                    al[mt][2] = Ql[r0 + 4];   al[mt][3] = Ql[r0 + 292];
                }
                uint32_t bh2[2][2], bl2[2][2];
#pragma unroll
                for (int nt = 0; nt < 2; nt++) {
                    int jb = (wn * 16 + nt * 8 + g) * 36 + ks * 8 + tg;
                    bh2[nt][0] = Kh[jb]; bh2[nt][1] = Kh[jb + 4];
                    bl2[nt][0] = Kl[jb]; bl2[nt][1] = Kl[jb + 4];
                }
#pragma unroll
                for (int mt = 0; mt < 4; mt++)
#pragma unroll
                    for (int nt = 0; nt < 2; nt++) {
                        mma_bf16(sc[mt][nt], ah[mt], bh2[nt]);
                        mma_bf16(sc[mt][nt], al[mt], bh2[nt]);
                        mma_bf16(sc[mt][nt], ah[mt], bl2[nt]);
                    }
            }
#pragma unroll
            for (int mt = 0; mt < 4; mt++) {
                int r = wm * 64 + mt * 16 + g;
#pragma unroll
                for (int nt = 0; nt < 2; nt++) {
                    int c = wn * 16 + nt * 8 + 2 * tg;
                    *(float2*)&S[r * 68 + c] =
                        make_float2(sc[mt][nt][0], sc[mt][nt][1]);
                    *(float2*)&S[(r + 8) * 68 + c] =
                        make_float2(sc[mt][nt][2], sc[mt][nt][3]);
                }
            }
        }
        __syncthreads();

        // ---- online softmax; write P as packed bf16 hi/lo pairs
        {
            int row = tid >> 1;
            int hf = tid & 1;
            const float4* p4 = (const float4*)&S[row * 68 + hf * 32];
            float4 v[8];
#pragma unroll
            for (int i = 0; i < 8; i++) v[i] = p4[i];
            float mx = -1e30f;
            const float* pv = (const float*)v;
#pragma unroll
            for (int c = 0; c < 32; c++) mx = fmaxf(mx, pv[c]);
            mx = fmaxf(mx, __shfl_xor_sync(0xffffffffu, mx, 1));
            float mo = s_m[row];
            float mn = fmaxf(mo, mx);
            float sum = 0.0f;
#pragma unroll
            for (int c = 0; c < 16; c++) {
                float e0 = __expf(pv[2 * c] - mn);
                float e1 = __expf(pv[2 * c + 1] - mn);
                sum += e0 + e1;
                Ph[row * 36 + hf * 16 + c] = pack_hi(e0, e1);
                Pl[row * 36 + hf * 16 + c] =
                    pack_hi(e0 - hi_part(e0), e1 - hi_part(e1));
            }
            sum += __shfl_xor_sync(0xffffffffu, sum, 1);
            if (hf == 0) {
                float a = __expf(mo - mn);
                s_a[row] = a;
                s_l[row] = s_l[row] * a + sum;
                s_m[row] = mn;
            }
        }
        __syncthreads();

        // ---- O = O*alpha + P @ V  (3 MMAs: ph*vh + pl*vh + ph*vl)
        {
#pragma unroll
            for (int mt = 0; mt < 4; mt++) {
                int r = wm * 64 + mt * 16 + g;
                float a0 = s_a[r], a1 = s_a[r + 8];
#pragma unroll
                for (int nt = 0; nt < 2; nt++) {
                    oacc[mt][nt][0] *= a0; oacc[mt][nt][1] *= a0;
                    oacc[mt][nt][2] *= a1; oacc[mt][nt][3] *= a1;
                }
            }
#pragma unroll
            for (int ks = 0; ks < 4; ks++) {
                uint32_t pah[4][4], pal[4][4];
#pragma unroll
                for (int mt = 0; mt < 4; mt++) {
                    int r0 = (wm * 64 + mt * 16 + g) * 36 + ks * 8 + tg;
                    pah[mt][0] = Ph[r0];     pah[mt][1] = Ph[r0 + 288];
                    pah[mt][2] = Ph[r0 + 4]; pah[mt][3] = Ph[r0 + 292];
                    pal[mt][0] = Pl[r0];     pal[mt][1] = Pl[r0 + 288];
                    pal[mt][2] = Pl[r0 + 4]; pal[mt][3] = Pl[r0 + 292];
                }
                uint32_t vbh[2][2], vbl[2][2];
#pragma unroll
                for (int nt = 0; nt < 2; nt++) {
                    int db = (wn * 16 + nt * 8 + g) * 36 + ks * 8 + tg;
                    vbh[nt][0] = Vh[db]; vbh[nt][1] = Vh[db + 4];
                    vbl[nt][0] = Vl[db]; vbl[nt][1] = Vl[db + 4];
                }
#pragma unroll
                for (int mt = 0; mt < 4; mt++)
#pragma unroll
                    for (int nt = 0; nt < 2; nt++) {
                        mma_bf16(oacc[mt][nt], pah[mt], vbh[nt]);
                        mma_bf16(oacc[mt][nt], pal[mt], vbh[nt]);
                        mma_bf16(oacc[mt][nt], pah[mt], vbl[nt]);
                    }
            }
        }
        __syncthreads();
    }

    // ---- finalize: divide by l, write [B,L,E]
    {
        float* Og = O + (size_t)(b * L_SEQ + q0) * E_DIM + h * D_HEAD;
#pragma unroll
        for (int mt = 0; mt < 4; mt++) {
            int r = wm * 64 + mt * 16 + g;
            float i0 = 1.0f / s_l[r];
            float i1 = 1.0f / s_l[r + 8];
#pragma unroll
            for (int nt = 0; nt < 2; nt++) {
                int c = wn * 16 + nt * 8 + 2 * tg;
                *(float2*)(Og + (size_t)r * E_DIM + c) =
                    make_float2(oacc[mt][nt][0] * i0, oacc[mt][nt][1] * i0);
                *(float2*)(Og + (size_t)(r + 8) * E_DIM + c) =
                    make_float2(oacc[mt][nt][2] * i1, oacc[mt][nt][3] * i1);
            }
        }
    }
}

// ---------------- launch -----------------------------------------------------
extern "C" void kernel_launch(void* const* d_in, const int* in_sizes, int n_in,
                              void* d_out, int out_size) {
    (void)in_sizes; (void)n_in; (void)out_size;
    const float* x   = (const float*)d_in[0];
    const float* ctx = (const float*)d_in[1];
    const float* Wq  = (const float*)d_in[2];
    const float* bq  = (const float*)d_in[3];
    const float* Wk  = (const float*)d_in[4];
    const float* bk  = (const float*)d_in[5];
    const float* Wv  = (const float*)d_in[6];
    const float* bv  = (const float*)d_in[7];
    const float* Wp  = (const float*)d_in[8];
    const float* bp  = (const float*)d_in[9];
    float* out = (float*)d_out;

    float *pQ, *pK, *pV, *pAO, *pWt;
    cudaGetSymbolAddress((void**)&pQ, g_Q);
    cudaGetSymbolAddress((void**)&pK, g_K);
    cudaGetSymbolAddress((void**)&pV, g_V);
    cudaGetSymbolAddress((void**)&pAO, g_AO);
    cudaGetSymbolAddress((void**)&pWt, g_Wt);
    float* WtQ = pWt + 0 * (size_t)E_DIM * E_DIM;
    float* WtK = pWt + 1 * (size_t)E_DIM * E_DIM;
    float* WtV = pWt + 2 * (size_t)E_DIM * E_DIM;
    float* WtP = pWt + 3 * (size_t)E_DIM * E_DIM;

    cudaFuncSetAttribute(gemm_mma, cudaFuncAttributeMaxDynamicSharedMemorySize,
                         GEMM_SMEM);
    cudaFuncSetAttribute(attn_mma, cudaFuncAttributeMaxDynamicSharedMemorySize,
                         ATTN_SMEM);

    dim3 tGrid(E_DIM / 32, E_DIM / 32);
    dim3 tBlk(32, 8);
    transpose_kernel<<<tGrid, tBlk>>>(Wq, WtQ);
    transpose_kernel<<<tGrid, tBlk>>>(Wk, WtK);
    transpose_kernel<<<tGrid, tBlk>>>(Wv, WtV);
    transpose_kernel<<<tGrid, tBlk>>>(Wp, WtP);

    dim3 gGemm(E_DIM / 128, M_ROWS / 128);   // (8, 32)
    gemm_mma<<<gGemm, 256, GEMM_SMEM>>>(x,   WtQ, bq, pQ);
    gemm_mma<<<gGemm, 256, GEMM_SMEM>>>(ctx, WtK, bk, pK);
    gemm_mma<<<gGemm, 256, GEMM_SMEM>>>(ctx, WtV, bv, pV);

    dim3 gAttn(L_SEQ / 128, B_SZ * H_NUM);   // (16, 32)
    attn_mma<<<gAttn, 256, ATTN_SMEM>>>(pQ, pK, pV, pAO);

    gemm_mma<<<gGemm, 256, GEMM_SMEM>>>(pAO, WtP, bp, out);
}

// round 11
// speedup vs baseline: 2.4534x; 1.1179x over previous
#include <cuda_runtime.h>
#include <math.h>
#include <stdint.h>

// Problem constants
#define E_DIM 1024
#define H_NUM 16
#define D_HEAD 64
#define B_SZ 2
#define L_SEQ 2048
#define S_SEQ 2048
#define M_ROWS (B_SZ * L_SEQ)   // 4096

// ---------------- scratch (device globals; no allocations allowed) -----------
__device__ float g_Q[B_SZ * L_SEQ * E_DIM];
__device__ float g_K[B_SZ * S_SEQ * E_DIM];
__device__ float g_V[B_SZ * S_SEQ * E_DIM];
__device__ float g_AO[B_SZ * L_SEQ * E_DIM];
__device__ float g_Wt[4][E_DIM * E_DIM];   // transposed weights [N][K]

// ---------------- helpers ----------------------------------------------------
__device__ __forceinline__ uint32_t f2tf32(float x) {
    uint32_t r;
    asm("cvt.rna.tf32.f32 %0, %1;" : "=r"(r) : "f"(x));
    return r;
}

__device__ __forceinline__ void mma_tf32(float c[4], const uint32_t a[4],
                                         const uint32_t b[2]) {
    asm volatile(
        "mma.sync.aligned.m16n8k8.row.col.f32.tf32.tf32.f32 "
        "{%0,%1,%2,%3}, {%4,%5,%6,%7}, {%8,%9}, {%0,%1,%2,%3};"
        : "+f"(c[0]), "+f"(c[1]), "+f"(c[2]), "+f"(c[3])
        : "r"(a[0]), "r"(a[1]), "r"(a[2]), "r"(a[3]), "r"(b[0]), "r"(b[1]));
}

__device__ __forceinline__ void mma_bf16(float c[4], const uint32_t a[4],
                                         const uint32_t b[2]) {
    asm volatile(
        "mma.sync.aligned.m16n8k16.row.col.f32.bf16.bf16.f32 "
        "{%0,%1,%2,%3}, {%4,%5,%6,%7}, {%8,%9}, {%0,%1,%2,%3};"
        : "+f"(c[0]), "+f"(c[1]), "+f"(c[2]), "+f"(c[3])
        : "r"(a[0]), "r"(a[1]), "r"(a[2]), "r"(a[3]), "r"(b[0]), "r"(b[1]));
}

// bf16 split helpers: hi = truncate-to-bf16 (top 16 bits), lo = residual.
__device__ __forceinline__ float hi_part(float x) {
    return __uint_as_float(__float_as_uint(x) & 0xffff0000u);
}
// pack bf16(x0) into low half, bf16(x1) into high half (truncation)
__device__ __forceinline__ uint32_t pack_hi(float x0, float x1) {
    uint32_t u0 = __float_as_uint(x0), u1 = __float_as_uint(x1);
    return (u1 & 0xffff0000u) | (u0 >> 16);
}

// ---------------- weight transpose: Wt[n][k] = W[k][n] -----------------------
__global__ __launch_bounds__(256) void transpose_kernel(
    const float* __restrict__ W, float* __restrict__ Wt) {
    __shared__ float t[32][33];
    int x = blockIdx.x * 32 + threadIdx.x;
    int y0 = blockIdx.y * 32 + threadIdx.y;
#pragma unroll
    for (int j = 0; j < 32; j += 8)
        t[threadIdx.y + j][threadIdx.x] = W[(size_t)(y0 + j) * E_DIM + x];
    __syncthreads();
    int xo = blockIdx.y * 32 + threadIdx.x;
    int yo = blockIdx.x * 32 + threadIdx.y;
#pragma unroll
    for (int j = 0; j < 32; j += 8)
        Wt[(size_t)(yo + j) * E_DIM + xo] = t[threadIdx.x][threadIdx.y + j];
}

// ---------------- mma.sync tf32 GEMM (unchanged) -----------------------------
#define SPAD 36
#define GEMM_SMEM (4 * 128 * SPAD * 4)

__global__ __launch_bounds__(256) void gemm_mma(
    const float* __restrict__ A, const float* __restrict__ Bt,
    const float* __restrict__ bias, float* __restrict__ C) {
    extern __shared__ float gsm[];
    float* sA = gsm;
    float* sB = gsm + 2 * 128 * SPAD;

    const int tid = threadIdx.x;
    const int lane = tid & 31;
    const int wid = tid >> 5;
    const int g = lane >> 2;
    const int tg = lane & 3;
    const int wm = wid & 1;
    const int wn = wid >> 1;
    const int m0 = blockIdx.y * 128;
    const int n0 = blockIdx.x * 128;

    const int lrow = tid >> 3;
    const int lc4 = (tid & 7) * 4;

    float acc[4][4][4] = {};
    float4 ra[4], rb[4];

    const float* Ag = A + (size_t)(m0 + lrow) * 1024 + lc4;
    const float* Bg = Bt + (size_t)(n0 + lrow) * 1024 + lc4;

#pragma unroll
    for (int j = 0; j < 4; j++) {
        ra[j] = *(const float4*)(Ag + (size_t)j * 32 * 1024);
        rb[j] = *(const float4*)(Bg + (size_t)j * 32 * 1024);
    }

    for (int it = 0; it < 32; ++it) {
        {
            float* dA = sA + (it & 1) * 128 * SPAD;
            float* dB = sB + (it & 1) * 128 * SPAD;
#pragma unroll
            for (int j = 0; j < 4; j++) {
                uint4 ta = make_uint4(f2tf32(ra[j].x), f2tf32(ra[j].y),
                                      f2tf32(ra[j].z), f2tf32(ra[j].w));
                *(uint4*)&dA[(lrow + j * 32) * SPAD + lc4] = ta;
                uint4 tb = make_uint4(f2tf32(rb[j].x), f2tf32(rb[j].y),
                                      f2tf32(rb[j].z), f2tf32(rb[j].w));
                *(uint4*)&dB[(lrow + j * 32) * SPAD + lc4] = tb;
            }
        }
        __syncthreads();

        if (it + 1 < 32) {
            const float* An = Ag + (size_t)(it + 1) * 32;
            const float* Bn = Bg + (size_t)(it + 1) * 32;
#pragma unroll
            for (int j = 0; j < 4; j++) {
                ra[j] = *(const float4*)(An + (size_t)j * 32 * 1024);
                rb[j] = *(const float4*)(Bn + (size_t)j * 32 * 1024);
            }
        }

        {
            const uint32_t* cA = (const uint32_t*)(sA + (it & 1) * 128 * SPAD);
            const uint32_t* cB = (const uint32_t*)(sB + (it & 1) * 128 * SPAD);
#pragma unroll
            for (int ks = 0; ks < 4; ks++) {
                const int kb = ks * 8;
                uint32_t af[4][4];
#pragma unroll
                for (int mt = 0; mt < 4; mt++) {
                    const int r = wm * 64 + mt * 16 + g;
                    af[mt][0] = cA[r * SPAD + kb + tg];
                    af[mt][1] = cA[(r + 8) * SPAD + kb + tg];
                    af[mt][2] = cA[r * SPAD + kb + tg + 4];
                    af[mt][3] = cA[(r + 8) * SPAD + kb + tg + 4];
                }
                uint32_t bf[4][2];
#pragma unroll
                for (int nt = 0; nt < 4; nt++) {
                    const int c = wn * 32 + nt * 8 + g;
                    bf[nt][0] = cB[c * SPAD + kb + tg];
                    bf[nt][1] = cB[c * SPAD + kb + tg + 4];
                }
#pragma unroll
                for (int mt = 0; mt < 4; mt++)
#pragma unroll
                    for (int nt = 0; nt < 4; nt++)
                        mma_tf32(acc[mt][nt], af[mt], bf[nt]);
            }
        }
        __syncthreads();
    }

#pragma unroll
    for (int mt = 0; mt < 4; mt++) {
        const int row = m0 + wm * 64 + mt * 16 + g;
#pragma unroll
        for (int nt = 0; nt < 4; nt++) {
            const int col = n0 + wn * 32 + nt * 8 + tg * 2;
            const float2 bv = *(const float2*)&bias[col];
            float2 o0, o1;
            o0.x = acc[mt][nt][0] + bv.x;
            o0.y = acc[mt][nt][1] + bv.y;
            o1.x = acc[mt][nt][2] + bv.x;
            o1.y = acc[mt][nt][3] + bv.y;
            *(float2*)(C + (size_t)row * 1024 + col) = o0;
            *(float2*)(C + (size_t)(row + 8) * 1024 + col) = o1;
        }
    }
}

// ---------------- Flash attention, register-resident softmax -----------------
// CTA: 128 queries, 64 keys/iter, 8 warps (wm = 64-row half, wn = 16-col slice)
// Softmax stays in MMA accumulators; log2-domain (Q pre-scaled by 0.125*log2e).
// smem (u32): Qh/Ql[128][36], Kh/Kl[64][36], Vh/Vl[64][36], Ph/Pl[128][36],
//             Rm/Rs[128][4] f32, s_m[128], s_l[128]  = 115,712 B -> 2 CTAs/SM.
#define AQH 0
#define AQL 4608
#define AKH 9216
#define AKL 11520
#define AVH 13824
#define AVL 16128
#define APH 18432
#define APL 23040
#define ARM 27648
#define ARS 28160
#define ASM 28672
#define ASL 28800
#define ATTN_SMEM (28928 * 4)

__global__ __launch_bounds__(256, 2) void attn_mma(
    const float* __restrict__ Q, const float* __restrict__ K,
    const float* __restrict__ V, float* __restrict__ O) {
    extern __shared__ uint32_t smu[];
    uint32_t* Qh = smu + AQH;
    uint32_t* Ql = smu + AQL;
    uint32_t* Kh = smu + AKH;
    uint32_t* Kl = smu + AKL;
    uint32_t* Vh = smu + AVH;
    uint32_t* Vl = smu + AVL;
    uint32_t* Ph = smu + APH;
    uint32_t* Pl = smu + APL;
    float* Rm  = (float*)(smu + ARM);
    float* Rs  = (float*)(smu + ARS);
    float* s_m = (float*)(smu + ASM);
    float* s_l = (float*)(smu + ASL);

    const int tid = threadIdx.x;
    const int lane = tid & 31;
    const int wid = tid >> 5;
    const int g = lane >> 2;
    const int tg = lane & 3;
    const int wm = wid & 1;       // 64-row half
    const int wn = wid >> 1;      // 16-col slice
    const int bh = blockIdx.y;
    const int b = bh >> 4;
    const int h = bh & 15;
    const int q0 = blockIdx.x * 128;

    const float* Qg = Q + (size_t)(b * L_SEQ + q0) * E_DIM + h * D_HEAD;
    const float* Kg0 = K + (size_t)b * S_SEQ * E_DIM + h * D_HEAD;
    const float* Vg0 = V + (size_t)b * S_SEQ * E_DIM + h * D_HEAD;

    // Q: pre-scale by (1/8)*log2(e) so softmax works in exp2 domain.
    const float QSCALE = 0.125f * 1.4426950408889634f;
#pragma unroll
    for (int p = 0; p < 16; p++) {
        int idx = tid + p * 256;
        int r = idx >> 5;
        int dp = idx & 31;
        float2 q = *(const float2*)(Qg + (size_t)r * E_DIM + 2 * dp);
        float x0 = q.x * QSCALE, x1 = q.y * QSCALE;
        Qh[r * 36 + dp] = pack_hi(x0, x1);
        Ql[r * 36 + dp] = pack_hi(x0 - hi_part(x0), x1 - hi_part(x1));
    }
    if (tid < 128) { s_m[tid] = -1e30f; s_l[tid] = 0.0f; }

    float oacc[4][2][4] = {};

    for (int t = 0; t < S_SEQ / 64; ++t) {
        const float* Kg = Kg0 + (size_t)t * 64 * E_DIM;
        const float* Vg = Vg0 + (size_t)t * 64 * E_DIM;
#pragma unroll
        for (int p = 0; p < 8; p++) {
            int idx = tid + p * 256;
            int j = idx >> 5;
            int dp = idx & 31;
            float2 kv = *(const float2*)(Kg + (size_t)j * E_DIM + 2 * dp);
            Kh[j * 36 + dp] = pack_hi(kv.x, kv.y);
            Kl[j * 36 + dp] = pack_hi(kv.x - hi_part(kv.x), kv.y - hi_part(kv.y));
        }
#pragma unroll
        for (int p = 0; p < 8; p++) {
            int idx = tid + p * 256;
            int d = idx & 63;
            int jp = idx >> 6;
            float v0 = Vg[(size_t)(2 * jp) * E_DIM + d];
            float v1 = Vg[(size_t)(2 * jp + 1) * E_DIM + d];
            Vh[d * 36 + jp] = pack_hi(v0, v1);
            Vl[d * 36 + jp] = pack_hi(v0 - hi_part(v0), v1 - hi_part(v1));
        }
        __syncthreads();   // (A) tiles ready

        // ---- QK^T in registers: sc[mt][nt][4]
        float sc[4][2][4] = {};
#pragma unroll
        for (int ks = 0; ks < 4; ks++) {
            uint32_t ah[4][4], al[4][4];
#pragma unroll
            for (int mt = 0; mt < 4; mt++) {
                int r0 = (wm * 64 + mt * 16 + g) * 36 + ks * 8 + tg;
                ah[mt][0] = Qh[r0];       ah[mt][1] = Qh[r0 + 288];
                ah[mt][2] = Qh[r0 + 4];   ah[mt][3] = Qh[r0 + 292];
                al[mt][0] = Ql[r0];       al[mt][1] = Ql[r0 + 288];
                al[mt][2] = Ql[r0 + 4];   al[mt][3] = Ql[r0 + 292];
            }
            uint32_t bh2[2][2], bl2[2][2];
#pragma unroll
            for (int nt = 0; nt < 2; nt++) {
                int jb = (wn * 16 + nt * 8 + g) * 36 + ks * 8 + tg;
                bh2[nt][0] = Kh[jb]; bh2[nt][1] = Kh[jb + 4];
                bl2[nt][0] = Kl[jb]; bl2[nt][1] = Kl[jb + 4];
            }
#pragma unroll
            for (int mt = 0; mt < 4; mt++)
#pragma unroll
                for (int nt = 0; nt < 2; nt++) {
                    mma_bf16(sc[mt][nt], ah[mt], bh2[nt]);
                    mma_bf16(sc[mt][nt], al[mt], bh2[nt]);
                    mma_bf16(sc[mt][nt], ah[mt], bl2[nt]);
                }
        }

        // ---- row max: quad shfl + cross-warp via Rm
        float mloc[4][2];
#pragma unroll
        for (int mt = 0; mt < 4; mt++) {
            mloc[mt][0] = fmaxf(fmaxf(sc[mt][0][0], sc[mt][0][1]),
                                fmaxf(sc[mt][1][0], sc[mt][1][1]));
            mloc[mt][1] = fmaxf(fmaxf(sc[mt][0][2], sc[mt][0][3]),
                                fmaxf(sc[mt][1][2], sc[mt][1][3]));
        }
#pragma unroll
        for (int mt = 0; mt < 4; mt++)
#pragma unroll
            for (int hf = 0; hf < 2; hf++) {
                float v = mloc[mt][hf];
                v = fmaxf(v, __shfl_xor_sync(0xffffffffu, v, 1));
                v = fmaxf(v, __shfl_xor_sync(0xffffffffu, v, 2));
                mloc[mt][hf] = v;
            }
        if (tg == 0) {
#pragma unroll
            for (int mt = 0; mt < 4; mt++)
#pragma unroll
                for (int hf = 0; hf < 2; hf++)
                    Rm[(wm * 64 + mt * 16 + hf * 8 + g) * 4 + wn] = mloc[mt][hf];
        }
        __syncthreads();   // (B) partial maxes visible

        float mnew[4][2], mold[4][2];
#pragma unroll
        for (int mt = 0; mt < 4; mt++)
#pragma unroll
            for (int hf = 0; hf < 2; hf++) {
                int row = wm * 64 + mt * 16 + hf * 8 + g;
                float4 r4 = *(const float4*)&Rm[row * 4];
                float mx = fmaxf(fmaxf(r4.x, r4.y), fmaxf(r4.z, r4.w));
                float mo = s_m[row];
                mold[mt][hf] = mo;
                mnew[mt][hf] = fmaxf(mo, mx);
            }

        // rescale O by alpha (computed per-thread; log2 domain)
#pragma unroll
        for (int mt = 0; mt < 4; mt++) {
            float a0 = exp2f(mold[mt][0] - mnew[mt][0]);
            float a1 = exp2f(mold[mt][1] - mnew[mt][1]);
#pragma unroll
            for (int nt = 0; nt < 2; nt++) {
                oacc[mt][nt][0] *= a0; oacc[mt][nt][1] *= a0;
                oacc[mt][nt][2] *= a1; oacc[mt][nt][3] *= a1;
            }
        }

        // exp2, pack P directly from accumulators, accumulate local sums
        float lsum[4][2];
#pragma unroll
        for (int mt = 0; mt < 4; mt++) { lsum[mt][0] = 0.f; lsum[mt][1] = 0.f; }
#pragma unroll
        for (int mt = 0; mt < 4; mt++) {
            int r0 = (wm * 64 + mt * 16 + g) * 36 + wn * 8 + tg;
#pragma unroll
            for (int nt = 0; nt < 2; nt++) {
                float e0 = exp2f(sc[mt][nt][0] - mnew[mt][0]);
                float e1 = exp2f(sc[mt][nt][1] - mnew[mt][0]);
                float e2 = exp2f(sc[mt][nt][2] - mnew[mt][1]);
                float e3 = exp2f(sc[mt][nt][3] - mnew[mt][1]);
                lsum[mt][0] += e0 + e1;
                lsum[mt][1] += e2 + e3;
                Ph[r0 + nt * 4] = pack_hi(e0, e1);
                Pl[r0 + nt * 4] = pack_hi(e0 - hi_part(e0), e1 - hi_part(e1));
                Ph[r0 + 288 + nt * 4] = pack_hi(e2, e3);
                Pl[r0 + 288 + nt * 4] = pack_hi(e2 - hi_part(e2), e3 - hi_part(e3));
            }
        }
#pragma unroll
        for (int mt = 0; mt < 4; mt++)
#pragma unroll
            for (int hf = 0; hf < 2; hf++) {
                float v = lsum[mt][hf];
                v += __shfl_xor_sync(0xffffffffu, v, 1);
                v += __shfl_xor_sync(0xffffffffu, v, 2);
                lsum[mt][hf] = v;
            }
        if (tg == 0) {
#pragma unroll
            for (int mt = 0; mt < 4; mt++)
#pragma unroll
                for (int hf = 0; hf < 2; hf++)
                    Rs[(wm * 64 + mt * 16 + hf * 8 + g) * 4 + wn] = lsum[mt][hf];
        }
        __syncthreads();   // (C) sums + P visible

        // update running l, m (one writer per row: wn==0, tg==0)
        if (wn == 0 && tg == 0) {
#pragma unroll
            for (int mt = 0; mt < 4; mt++)
#pragma unroll
                for (int hf = 0; hf < 2; hf++) {
                    int row = wm * 64 + mt * 16 + hf * 8 + g;
                    float4 r4 = *(const float4*)&Rs[row * 4];
                    float sum = (r4.x + r4.y) + (r4.z + r4.w);
                    float a = exp2f(mold[mt][hf] - mnew[mt][hf]);
                    s_l[row] = s_l[row] * a + sum;
                    s_m[row] = mnew[mt][hf];
                }
        }

        // ---- O += P @ V (3-MMA split)
#pragma unroll
        for (int ks = 0; ks < 4; ks++) {
            uint32_t pah[4][4], pal[4][4];
#pragma unroll
            for (int mt = 0; mt < 4; mt++) {
                int r0 = (wm * 64 + mt * 16 + g) * 36 + ks * 8 + tg;
                pah[mt][0] = Ph[r0];     pah[mt][1] = Ph[r0 + 288];
                pah[mt][2] = Ph[r0 + 4]; pah[mt][3] = Ph[r0 + 292];
                pal[mt][0] = Pl[r0];     pal[mt][1] = Pl[r0 + 288];
                pal[mt][2] = Pl[r0 + 4]; pal[mt][3] = Pl[r0 + 292];
            }
            uint32_t vbh[2][2], vbl[2][2];
#pragma unroll
            for (int nt = 0; nt < 2; nt++) {
                int db = (wn * 16 + nt * 8 + g) * 36 + ks * 8 + tg;
                vbh[nt][0] = Vh[db]; vbh[nt][1] = Vh[db + 4];
                vbl[nt][0] = Vl[db]; vbl[nt][1] = Vl[db + 4];
            }
#pragma unroll
            for (int mt = 0; mt < 4; mt++)
#pragma unroll
                for (int nt = 0; nt < 2; nt++) {
                    mma_bf16(oacc[mt][nt], pah[mt], vbh[nt]);
                    mma_bf16(oacc[mt][nt], pal[mt], vbh[nt]);
                    mma_bf16(oacc[mt][nt], pah[mt], vbl[nt]);
                }
        }
        __syncthreads();   // (E) protect K/V/P tiles for next iter
    }

    // ---- finalize: divide by l, write [B,L,E]
    {
        float* Og = O + (size_t)(b * L_SEQ + q0) * E_DIM + h * D_HEAD;
#pragma unroll
        for (int mt = 0; mt < 4; mt++) {
            int r = wm * 64 + mt * 16 + g;
            float i0 = 1.0f / s_l[r];
            float i1 = 1.0f / s_l[r + 8];
#pragma unroll
            for (int nt = 0; nt < 2; nt++) {
                int c = wn * 16 + nt * 8 + 2 * tg;
                *(float2*)(Og + (size_t)r * E_DIM + c) =
                    make_float2(oacc[mt][nt][0] * i0, oacc[mt][nt][1] * i0);
                *(float2*)(Og + (size_t)(r + 8) * E_DIM + c) =
                    make_float2(oacc[mt][nt][2] * i1, oacc[mt][nt][3] * i1);
            }
        }
    }
}

// ---------------- launch -----------------------------------------------------
extern "C" void kernel_launch(void* const* d_in, const int* in_sizes, int n_in,
                              void* d_out, int out_size) {
    (void)in_sizes; (void)n_in; (void)out_size;
    const float* x   = (const float*)d_in[0];
    const float* ctx = (const float*)d_in[1];
    const float* Wq  = (const float*)d_in[2];
    const float* bq  = (const float*)d_in[3];
    const float* Wk  = (const float*)d_in[4];
    const float* bk  = (const float*)d_in[5];
    const float* Wv  = (const float*)d_in[6];
    const float* bv  = (const float*)d_in[7];
    const float* Wp  = (const float*)d_in[8];
    const float* bp  = (const float*)d_in[9];
    float* out = (float*)d_out;

    float *pQ, *pK, *pV, *pAO, *pWt;
    cudaGetSymbolAddress((void**)&pQ, g_Q);
    cudaGetSymbolAddress((void**)&pK, g_K);
    cudaGetSymbolAddress((void**)&pV, g_V);
    cudaGetSymbolAddress((void**)&pAO, g_AO);
    cudaGetSymbolAddress((void**)&pWt, g_Wt);
    float* WtQ = pWt + 0 * (size_t)E_DIM * E_DIM;
    float* WtK = pWt + 1 * (size_t)E_DIM * E_DIM;
    float* WtV = pWt + 2 * (size_t)E_DIM * E_DIM;
    float* WtP = pWt + 3 * (size_t)E_DIM * E_DIM;

    cudaFuncSetAttribute(gemm_mma, cudaFuncAttributeMaxDynamicSharedMemorySize,
                         GEMM_SMEM);
    cudaFuncSetAttribute(attn_mma, cudaFuncAttributeMaxDynamicSharedMemorySize,
                         ATTN_SMEM);

    dim3 tGrid(E_DIM / 32, E_DIM / 32);
    dim3 tBlk(32, 8);
    transpose_kernel<<<tGrid, tBlk>>>(Wq, WtQ);
    transpose_kernel<<<tGrid, tBlk>>>(Wk, WtK);
    transpose_kernel<<<tGrid, tBlk>>>(Wv, WtV);
    transpose_kernel<<<tGrid, tBlk>>>(Wp, WtP);

    dim3 gGemm(E_DIM / 128, M_ROWS / 128);   // (8, 32)
    gemm_mma<<<gGemm, 256, GEMM_SMEM>>>(x,   WtQ, bq, pQ);
    gemm_mma<<<gGemm, 256, GEMM_SMEM>>>(ctx, WtK, bk, pK);
    gemm_mma<<<gGemm, 256, GEMM_SMEM>>>(ctx, WtV, bv, pV);

    dim3 gAttn(L_SEQ / 128, B_SZ * H_NUM);   // (16, 32)
    attn_mma<<<gAttn, 256, ATTN_SMEM>>>(pQ, pK, pV, pAO);

    gemm_mma<<<gGemm, 256, GEMM_SMEM>>>(pAO, WtP, bp, out);
}

// round 12
// speedup vs baseline: 2.6366x; 1.0747x over previous
#include <cuda_runtime.h>
#include <math.h>
#include <stdint.h>

// Problem constants
#define E_DIM 1024
#define H_NUM 16
#define D_HEAD 64
#define B_SZ 2
#define L_SEQ 2048
#define S_SEQ 2048
#define M_ROWS (B_SZ * L_SEQ)   // 4096

// ---------------- scratch (device globals; no allocations allowed) -----------
__device__ float g_Q[B_SZ * L_SEQ * E_DIM];
__device__ float g_K[B_SZ * S_SEQ * E_DIM];
__device__ float g_V[B_SZ * S_SEQ * E_DIM];
__device__ float g_AO[B_SZ * L_SEQ * E_DIM];

// ---------------- helpers ----------------------------------------------------
__device__ __forceinline__ uint32_t smem_u32(const void* p) {
    uint32_t a;
    asm("{ .reg .u64 t; cvta.to.shared.u64 t, %1; cvt.u32.u64 %0, t; }"
        : "=r"(a) : "l"(p));
    return a;
}

__device__ __forceinline__ uint32_t f2tf32(float x) {
    uint32_t r;
    asm("cvt.rna.tf32.f32 %0, %1;" : "=r"(r) : "f"(x));
    return r;
}

#define CP_ASYNC16(dst, src) \
    asm volatile("cp.async.cg.shared.global [%0], [%1], 16;" \
                 :: "r"(dst), "l"(src) : "memory")
#define CP_COMMIT() asm volatile("cp.async.commit_group;" ::: "memory")
#define CP_WAIT(n)  asm volatile("cp.async.wait_group %0;" :: "n"(n) : "memory")

__device__ __forceinline__ void mma_tf32(float c[4], const uint32_t a[4],
                                         const uint32_t b[2]) {
    asm volatile(
        "mma.sync.aligned.m16n8k8.row.col.f32.tf32.tf32.f32 "
        "{%0,%1,%2,%3}, {%4,%5,%6,%7}, {%8,%9}, {%0,%1,%2,%3};"
        : "+f"(c[0]), "+f"(c[1]), "+f"(c[2]), "+f"(c[3])
        : "r"(a[0]), "r"(a[1]), "r"(a[2]), "r"(a[3]), "r"(b[0]), "r"(b[1]));
}

__device__ __forceinline__ void mma_bf16(float c[4], const uint32_t a[4],
                                         const uint32_t b[2]) {
    asm volatile(
        "mma.sync.aligned.m16n8k16.row.col.f32.bf16.bf16.f32 "
        "{%0,%1,%2,%3}, {%4,%5,%6,%7}, {%8,%9}, {%0,%1,%2,%3};"
        : "+f"(c[0]), "+f"(c[1]), "+f"(c[2]), "+f"(c[3])
        : "r"(a[0]), "r"(a[1]), "r"(a[2]), "r"(a[3]), "r"(b[0]), "r"(b[1]));
}

// bf16 split helpers: hi = truncate-to-bf16 (top 16 bits), lo = residual.
__device__ __forceinline__ float hi_part(float x) {
    return __uint_as_float(__float_as_uint(x) & 0xffff0000u);
}
__device__ __forceinline__ uint32_t pack_hi(float x0, float x1) {
    uint32_t u0 = __float_as_uint(x0), u1 = __float_as_uint(x1);
    return (u1 & 0xffff0000u) | (u0 >> 16);
}

// ---------------- mma.sync tf32 GEMM: C[M,1024] = A @ W + bias ---------------
// A row-major [M,K]; W row-major [K,N] loaded DIRECTLY (no pre-transpose).
// CTA 128x128, BK=32, 8 warps (2x4), warp tile 64x32.
// A: LDG -> cvt.rna.tf32 -> STS (pitch 36). B: cp.async raw fp32 (pitch 136),
// cvt.rna.tf32 applied on fragment registers. 2 CTAs/SM.
#define APITCH 36
#define BPITCH 136
#define GEMM_SMEM ((2 * 128 * APITCH + 2 * 32 * BPITCH) * 4)   // 71680 B

__global__ __launch_bounds__(256, 2) void gemm_mma(
    const float* __restrict__ A, const float* __restrict__ W,
    const float* __restrict__ bias, float* __restrict__ C) {
    extern __shared__ float gsm[];
    float* sA = gsm;                          // [2][128*36] (tf32 bits)
    float* sB = gsm + 2 * 128 * APITCH;       // [2][32*136] (raw fp32)

    const int tid = threadIdx.x;
    const int lane = tid & 31;
    const int wid = tid >> 5;
    const int g = lane >> 2;
    const int tg = lane & 3;
    const int wm = wid & 1;
    const int wn = wid >> 1;
    const int m0 = blockIdx.y * 128;
    const int n0 = blockIdx.x * 128;

    // A loader mapping: 128 rows x 32 cols, 8 threads/row (16B each)
    const int lrowA = tid >> 3;               // 0..31 (+ j*32)
    const int lc4A = (tid & 7) * 4;
    // B loader mapping: 32 rows x 128 cols, 32 threads/row (16B each)
    const int lrowB = tid >> 5;               // 0..7 (+ j*8)
    const int lc4B = (tid & 31) * 4;

    const float* Ag = A + (size_t)(m0 + lrowA) * 1024 + lc4A;
    const float* Wg = W + (size_t)lrowB * 1024 + n0 + lc4B;
    const uint32_t sBu = smem_u32(sB);

    float acc[4][4][4] = {};
    float4 ra[4];

    // prologue: prefetch A(0) into regs, B(0) via cp.async
#pragma unroll
    for (int j = 0; j < 4; j++)
        ra[j] = *(const float4*)(Ag + (size_t)j * 32 * 1024);
#pragma unroll
    for (int j = 0; j < 4; j++)
        CP_ASYNC16(sBu + (uint32_t)(((lrowB + j * 8) * BPITCH + lc4B) * 4),
                   Wg + (size_t)j * 8 * 1024);
    CP_COMMIT();

    for (int it = 0; it < 32; ++it) {
        // store A(it) (tf32-rounded) into buffer it&1
        {
            float* dA = sA + (it & 1) * 128 * APITCH;
#pragma unroll
            for (int j = 0; j < 4; j++) {
                uint4 ta = make_uint4(f2tf32(ra[j].x), f2tf32(ra[j].y),
                                      f2tf32(ra[j].z), f2tf32(ra[j].w));
                *(uint4*)&dA[(lrowA + j * 32) * APITCH + lc4A] = ta;
            }
        }
        // prefetch next chunk
        if (it + 1 < 32) {
            const float* An = Ag + (size_t)(it + 1) * 32;
#pragma unroll
            for (int j = 0; j < 4; j++)
                ra[j] = *(const float4*)(An + (size_t)j * 32 * 1024);
            const float* Wn = Wg + (size_t)(it + 1) * 32 * 1024;
            const uint32_t sbn = sBu + ((it + 1) & 1) * 32 * BPITCH * 4;
#pragma unroll
            for (int j = 0; j < 4; j++)
                CP_ASYNC16(sbn + (uint32_t)(((lrowB + j * 8) * BPITCH + lc4B) * 4),
                           Wn + (size_t)j * 8 * 1024);
            CP_COMMIT();
            CP_WAIT(1);
        } else {
            CP_WAIT(0);
        }
        __syncthreads();

        // compute from buffer it&1
        {
            const uint32_t* cA = (const uint32_t*)(sA + (it & 1) * 128 * APITCH);
            const float* cB = sB + (it & 1) * 32 * BPITCH;
#pragma unroll
            for (int ks = 0; ks < 4; ks++) {
                const int kb = ks * 8;
                uint32_t af[4][4];
#pragma unroll
                for (int mt = 0; mt < 4; mt++) {
                    const int r = wm * 64 + mt * 16 + g;
                    af[mt][0] = cA[r * APITCH + kb + tg];
                    af[mt][1] = cA[(r + 8) * APITCH + kb + tg];
                    af[mt][2] = cA[r * APITCH + kb + tg + 4];
                    af[mt][3] = cA[(r + 8) * APITCH + kb + tg + 4];
                }
                uint32_t bf[4][2];
#pragma unroll
                for (int nt = 0; nt < 4; nt++) {
                    const int c = wn * 32 + nt * 8 + g;
                    bf[nt][0] = f2tf32(cB[(kb + tg) * BPITCH + c]);
                    bf[nt][1] = f2tf32(cB[(kb + tg + 4) * BPITCH + c]);
                }
#pragma unroll
                for (int mt = 0; mt < 4; mt++)
#pragma unroll
                    for (int nt = 0; nt < 4; nt++)
                        mma_tf32(acc[mt][nt], af[mt], bf[nt]);
            }
        }
        __syncthreads();
    }

    // epilogue: bias + store
#pragma unroll
    for (int mt = 0; mt < 4; mt++) {
        const int row = m0 + wm * 64 + mt * 16 + g;
#pragma unroll
        for (int nt = 0; nt < 4; nt++) {
            const int col = n0 + wn * 32 + nt * 8 + tg * 2;
            const float2 bv = *(const float2*)&bias[col];
            float2 o0, o1;
            o0.x = acc[mt][nt][0] + bv.x;
            o0.y = acc[mt][nt][1] + bv.y;
            o1.x = acc[mt][nt][2] + bv.x;
            o1.y = acc[mt][nt][3] + bv.y;
            *(float2*)(C + (size_t)row * 1024 + col) = o0;
            *(float2*)(C + (size_t)(row + 8) * 1024 + col) = o1;
        }
    }
}

// ---------------- Flash attention, register-resident softmax (unchanged) -----
#define AQH 0
#define AQL 4608
#define AKH 9216
#define AKL 11520
#define AVH 13824
#define AVL 16128
#define APH 18432
#define APL 23040
#define ARM 27648
#define ARS 28160
#define ASM 28672
#define ASL 28800
#define ATTN_SMEM (28928 * 4)

__global__ __launch_bounds__(256, 2) void attn_mma(
    const float* __restrict__ Q, const float* __restrict__ K,
    const float* __restrict__ V, float* __restrict__ O) {
    extern __shared__ uint32_t smu[];
    uint32_t* Qh = smu + AQH;
    uint32_t* Ql = smu + AQL;
    uint32_t* Kh = smu + AKH;
    uint32_t* Kl = smu + AKL;
    uint32_t* Vh = smu + AVH;
    uint32_t* Vl = smu + AVL;
    uint32_t* Ph = smu + APH;
    uint32_t* Pl = smu + APL;
    float* Rm  = (float*)(smu + ARM);
    float* Rs  = (float*)(smu + ARS);
    float* s_m = (float*)(smu + ASM);
    float* s_l = (float*)(smu + ASL);

    const int tid = threadIdx.x;
    const int lane = tid & 31;
    const int wid = tid >> 5;
    const int g = lane >> 2;
    const int tg = lane & 3;
    const int wm = wid & 1;
    const int wn = wid >> 1;
    const int bh = blockIdx.y;
    const int b = bh >> 4;
    const int h = bh & 15;
    const int q0 = blockIdx.x * 128;

    const float* Qg = Q + (size_t)(b * L_SEQ + q0) * E_DIM + h * D_HEAD;
    const float* Kg0 = K + (size_t)b * S_SEQ * E_DIM + h * D_HEAD;
    const float* Vg0 = V + (size_t)b * S_SEQ * E_DIM + h * D_HEAD;

    const float QSCALE = 0.125f * 1.4426950408889634f;
#pragma unroll
    for (int p = 0; p < 16; p++) {
        int idx = tid + p * 256;
        int r = idx >> 5;
        int dp = idx & 31;
        float2 q = *(const float2*)(Qg + (size_t)r * E_DIM + 2 * dp);
        float x0 = q.x * QSCALE, x1 = q.y * QSCALE;
        Qh[r * 36 + dp] = pack_hi(x0, x1);
        Ql[r * 36 + dp] = pack_hi(x0 - hi_part(x0), x1 - hi_part(x1));
    }
    if (tid < 128) { s_m[tid] = -1e30f; s_l[tid] = 0.0f; }

    float oacc[4][2][4] = {};

    for (int t = 0; t < S_SEQ / 64; ++t) {
        const float* Kg = Kg0 + (size_t)t * 64 * E_DIM;
        const float* Vg = Vg0 + (size_t)t * 64 * E_DIM;
#pragma unroll
        for (int p = 0; p < 8; p++) {
            int idx = tid + p * 256;
            int j = idx >> 5;
            int dp = idx & 31;
            float2 kv = *(const float2*)(Kg + (size_t)j * E_DIM + 2 * dp);
            Kh[j * 36 + dp] = pack_hi(kv.x, kv.y);
            Kl[j * 36 + dp] = pack_hi(kv.x - hi_part(kv.x), kv.y - hi_part(kv.y));
        }
#pragma unroll
        for (int p = 0; p < 8; p++) {
            int idx = tid + p * 256;
            int d = idx & 63;
            int jp = idx >> 6;
            float v0 = Vg[(size_t)(2 * jp) * E_DIM + d];
            float v1 = Vg[(size_t)(2 * jp + 1) * E_DIM + d];
            Vh[d * 36 + jp] = pack_hi(v0, v1);
            Vl[d * 36 + jp] = pack_hi(v0 - hi_part(v0), v1 - hi_part(v1));
        }
        __syncthreads();

        float sc[4][2][4] = {};
#pragma unroll
        for (int ks = 0; ks < 4; ks++) {
            uint32_t ah[4][4], al[4][4];
#pragma unroll
            for (int mt = 0; mt < 4; mt++) {
                int r0 = (wm * 64 + mt * 16 + g) * 36 + ks * 8 + tg;
                ah[mt][0] = Qh[r0];       ah[mt][1] = Qh[r0 + 288];
                ah[mt][2] = Qh[r0 + 4];   ah[mt][3] = Qh[r0 + 292];
                al[mt][0] = Ql[r0];       al[mt][1] = Ql[r0 + 288];
                al[mt][2] = Ql[r0 + 4];   al[mt][3] = Ql[r0 + 292];
            }
            uint32_t bh2[2][2], bl2[2][2];
#pragma unroll
            for (int nt = 0; nt < 2; nt++) {
                int jb = (wn * 16 + nt * 8 + g) * 36 + ks * 8 + tg;
                bh2[nt][0] = Kh[jb]; bh2[nt][1] = Kh[jb + 4];
                bl2[nt][0] = Kl[jb]; bl2[nt][1] = Kl[jb + 4];
            }
#pragma unroll
            for (int mt = 0; mt < 4; mt++)
#pragma unroll
                for (int nt = 0; nt < 2; nt++) {
                    mma_bf16(sc[mt][nt], ah[mt], bh2[nt]);
                    mma_bf16(sc[mt][nt], al[mt], bh2[nt]);
                    mma_bf16(sc[mt][nt], ah[mt], bl2[nt]);
                }
        }

        float mloc[4][2];
#pragma unroll
        for (int mt = 0; mt < 4; mt++) {
            mloc[mt][0] = fmaxf(fmaxf(sc[mt][0][0], sc[mt][0][1]),
                                fmaxf(sc[mt][1][0], sc[mt][1][1]));
            mloc[mt][1] = fmaxf(fmaxf(sc[mt][0][2], sc[mt][0][3]),
                                fmaxf(sc[mt][1][2], sc[mt][1][3]));
        }
#pragma unroll
        for (int mt = 0; mt < 4; mt++)
#pragma unroll
            for (int hf = 0; hf < 2; hf++) {
                float v = mloc[mt][hf];
                v = fmaxf(v, __shfl_xor_sync(0xffffffffu, v, 1));
                v = fmaxf(v, __shfl_xor_sync(0xffffffffu, v, 2));
                mloc[mt][hf] = v;
            }
        if (tg == 0) {
#pragma unroll
            for (int mt = 0; mt < 4; mt++)
#pragma unroll
                for (int hf = 0; hf < 2; hf++)
                    Rm[(wm * 64 + mt * 16 + hf * 8 + g) * 4 + wn] = mloc[mt][hf];
        }
        __syncthreads();

        float mnew[4][2], mold[4][2];
#pragma unroll
        for (int mt = 0; mt < 4; mt++)
#pragma unroll
            for (int hf = 0; hf < 2; hf++) {
                int row = wm * 64 + mt * 16 + hf * 8 + g;
                float4 r4 = *(const float4*)&Rm[row * 4];
                float mx = fmaxf(fmaxf(r4.x, r4.y), fmaxf(r4.z, r4.w));
                float mo = s_m[row];
                mold[mt][hf] = mo;
                mnew[mt][hf] = fmaxf(mo, mx);
            }

#pragma unroll
        for (int mt = 0; mt < 4; mt++) {
            float a0 = exp2f(mold[mt][0] - mnew[mt][0]);
            float a1 = exp2f(mold[mt][1] - mnew[mt][1]);
#pragma unroll
            for (int nt = 0; nt < 2; nt++) {
                oacc[mt][nt][0] *= a0; oacc[mt][nt][1] *= a0;
                oacc[mt][nt][2] *= a1; oacc[mt][nt][3] *= a1;
            }
        }

        float lsum[4][2];
#pragma unroll
        for (int mt = 0; mt < 4; mt++) { lsum[mt][0] = 0.f; lsum[mt][1] = 0.f; }
#pragma unroll
        for (int mt = 0; mt < 4; mt++) {
            int r0 = (wm * 64 + mt * 16 + g) * 36 + wn * 8 + tg;
#pragma unroll
            for (int nt = 0; nt < 2; nt++) {
                float e0 = exp2f(sc[mt][nt][0] - mnew[mt][0]);
                float e1 = exp2f(sc[mt][nt][1] - mnew[mt][0]);
                float e2 = exp2f(sc[mt][nt][2] - mnew[mt][1]);
                float e3 = exp2f(sc[mt][nt][3] - mnew[mt][1]);
                lsum[mt][0] += e0 + e1;
                lsum[mt][1] += e2 + e3;
                Ph[r0 + nt * 4] = pack_hi(e0, e1);
                Pl[r0 + nt * 4] = pack_hi(e0 - hi_part(e0), e1 - hi_part(e1));
                Ph[r0 + 288 + nt * 4] = pack_hi(e2, e3);
                Pl[r0 + 288 + nt * 4] = pack_hi(e2 - hi_part(e2), e3 - hi_part(e3));
            }
        }
#pragma unroll
        for (int mt = 0; mt < 4; mt++)
#pragma unroll
            for (int hf = 0; hf < 2; hf++) {
                float v = lsum[mt][hf];
                v += __shfl_xor_sync(0xffffffffu, v, 1);
                v += __shfl_xor_sync(0xffffffffu, v, 2);
                lsum[mt][hf] = v;
            }
        if (tg == 0) {
#pragma unroll
            for (int mt = 0; mt < 4; mt++)
#pragma unroll
                for (int hf = 0; hf < 2; hf++)
                    Rs[(wm * 64 + mt * 16 + hf * 8 + g) * 4 + wn] = lsum[mt][hf];
        }
        __syncthreads();

        if (wn == 0 && tg == 0) {
#pragma unroll
            for (int mt = 0; mt < 4; mt++)
#pragma unroll
                for (int hf = 0; hf < 2; hf++) {
                    int row = wm * 64 + mt * 16 + hf * 8 + g;
                    float4 r4 = *(const float4*)&Rs[row * 4];
                    float sum = (r4.x + r4.y) + (r4.z + r4.w);
                    float a = exp2f(mold[mt][hf] - mnew[mt][hf]);
                    s_l[row] = s_l[row] * a + sum;
                    s_m[row] = mnew[mt][hf];
                }
        }

#pragma unroll
        for (int ks = 0; ks < 4; ks++) {
            uint32_t pah[4][4], pal[4][4];
#pragma unroll
            for (int mt = 0; mt < 4; mt++) {
                int r0 = (wm * 64 + mt * 16 + g) * 36 + ks * 8 + tg;
                pah[mt][0] = Ph[r0];     pah[mt][1] = Ph[r0 + 288];
                pah[mt][2] = Ph[r0 + 4]; pah[mt][3] = Ph[r0 + 292];
                pal[mt][0] = Pl[r0];     pal[mt][1] = Pl[r0 + 288];
                pal[mt][2] = Pl[r0 + 4]; pal[mt][3] = Pl[r0 + 292];
            }
            uint32_t vbh[2][2], vbl[2][2];
#pragma unroll
            for (int nt = 0; nt < 2; nt++) {
                int db = (wn * 16 + nt * 8 + g) * 36 + ks * 8 + tg;
                vbh[nt][0] = Vh[db]; vbh[nt][1] = Vh[db + 4];
                vbl[nt][0] = Vl[db]; vbl[nt][1] = Vl[db + 4];
            }
#pragma unroll
            for (int mt = 0; mt < 4; mt++)
#pragma unroll
                for (int nt = 0; nt < 2; nt++) {
                    mma_bf16(oacc[mt][nt], pah[mt], vbh[nt]);
                    mma_bf16(oacc[mt][nt], pal[mt], vbh[nt]);
                    mma_bf16(oacc[mt][nt], pah[mt], vbl[nt]);
                }
        }
        __syncthreads();
    }

    {
        float* Og = O + (size_t)(b * L_SEQ + q0) * E_DIM + h * D_HEAD;
#pragma unroll
        for (int mt = 0; mt < 4; mt++) {
            int r = wm * 64 + mt * 16 + g;
            float i0 = 1.0f / s_l[r];
            float i1 = 1.0f / s_l[r + 8];
#pragma unroll
            for (int nt = 0; nt < 2; nt++) {
                int c = wn * 16 + nt * 8 + 2 * tg;
                *(float2*)(Og + (size_t)r * E_DIM + c) =
                    make_float2(oacc[mt][nt][0] * i0, oacc[mt][nt][1] * i0);
                *(float2*)(Og + (size_t)(r + 8) * E_DIM + c) =
                    make_float2(oacc[mt][nt][2] * i1, oacc[mt][nt][3] * i1);
            }
        }
    }
}

// ---------------- launch -----------------------------------------------------
extern "C" void kernel_launch(void* const* d_in, const int* in_sizes, int n_in,
                              void* d_out, int out_size) {
    (void)in_sizes; (void)n_in; (void)out_size;
    const float* x   = (const float*)d_in[0];
    const float* ctx = (const float*)d_in[1];
    const float* Wq  = (const float*)d_in[2];
    const float* bq  = (const float*)d_in[3];
    const float* Wk  = (const float*)d_in[4];
    const float* bk  = (const float*)d_in[5];
    const float* Wv  = (const float*)d_in[6];
    const float* bv  = (const float*)d_in[7];
    const float* Wp  = (const float*)d_in[8];
    const float* bp  = (const float*)d_in[9];
    float* out = (float*)d_out;

    float *pQ, *pK, *pV, *pAO;
    cudaGetSymbolAddress((void**)&pQ, g_Q);
    cudaGetSymbolAddress((void**)&pK, g_K);
    cudaGetSymbolAddress((void**)&pV, g_V);
    cudaGetSymbolAddress((void**)&pAO, g_AO);

    cudaFuncSetAttribute(gemm_mma, cudaFuncAttributeMaxDynamicSharedMemorySize,
                         GEMM_SMEM);
    cudaFuncSetAttribute(attn_mma, cudaFuncAttributeMaxDynamicSharedMemorySize,
                         ATTN_SMEM);

    dim3 gGemm(E_DIM / 128, M_ROWS / 128);   // (8, 32)
    gemm_mma<<<gGemm, 256, GEMM_SMEM>>>(x,   Wq, bq, pQ);
    gemm_mma<<<gGemm, 256, GEMM_SMEM>>>(ctx, Wk, bk, pK);
    gemm_mma<<<gGemm, 256, GEMM_SMEM>>>(ctx, Wv, bv, pV);

    dim3 gAttn(L_SEQ / 128, B_SZ * H_NUM);   // (16, 32)
    attn_mma<<<gAttn, 256, ATTN_SMEM>>>(pQ, pK, pV, pAO);

    gemm_mma<<<gGemm, 256, GEMM_SMEM>>>(pAO, Wp, bp, out);
}

// round 13
// speedup vs baseline: 2.8996x; 1.0997x over previous
#include <cuda_runtime.h>
#include <math.h>
#include <stdint.h>

// Problem constants
#define E_DIM 1024
#define H_NUM 16
#define D_HEAD 64
#define B_SZ 2
#define L_SEQ 2048
#define S_SEQ 2048
#define M_ROWS (B_SZ * L_SEQ)   // 4096

// ---------------- scratch (device globals; no allocations allowed) -----------
__device__ float g_Q[B_SZ * L_SEQ * E_DIM];
__device__ float g_K[B_SZ * S_SEQ * E_DIM];
__device__ float g_V[B_SZ * S_SEQ * E_DIM];
__device__ float g_AO[B_SZ * L_SEQ * E_DIM];

// ---------------- helpers ----------------------------------------------------
__device__ __forceinline__ uint32_t smem_u32(const void* p) {
    uint32_t a;
    asm("{ .reg .u64 t; cvta.to.shared.u64 t, %1; cvt.u32.u64 %0, t; }"
        : "=r"(a) : "l"(p));
    return a;
}

__device__ __forceinline__ uint32_t f2tf32(float x) {
    uint32_t r;
    asm("cvt.rna.tf32.f32 %0, %1;" : "=r"(r) : "f"(x));
    return r;
}

#define CP_ASYNC16(dst, src) \
    asm volatile("cp.async.cg.shared.global [%0], [%1], 16;" \
                 :: "r"(dst), "l"(src) : "memory")
#define CP_COMMIT() asm volatile("cp.async.commit_group;" ::: "memory")
#define CP_WAIT(n)  asm volatile("cp.async.wait_group %0;" :: "n"(n) : "memory")

__device__ __forceinline__ void mma_tf32(float c[4], const uint32_t a[4],
                                         const uint32_t b[2]) {
    asm volatile(
        "mma.sync.aligned.m16n8k8.row.col.f32.tf32.tf32.f32 "
        "{%0,%1,%2,%3}, {%4,%5,%6,%7}, {%8,%9}, {%0,%1,%2,%3};"
        : "+f"(c[0]), "+f"(c[1]), "+f"(c[2]), "+f"(c[3])
        : "r"(a[0]), "r"(a[1]), "r"(a[2]), "r"(a[3]), "r"(b[0]), "r"(b[1]));
}

__device__ __forceinline__ void mma_bf16(float c[4], const uint32_t a[4],
                                         const uint32_t b[2]) {
    asm volatile(
        "mma.sync.aligned.m16n8k16.row.col.f32.bf16.bf16.f32 "
        "{%0,%1,%2,%3}, {%4,%5,%6,%7}, {%8,%9}, {%0,%1,%2,%3};"
        : "+f"(c[0]), "+f"(c[1]), "+f"(c[2]), "+f"(c[3])
        : "r"(a[0]), "r"(a[1]), "r"(a[2]), "r"(a[3]), "r"(b[0]), "r"(b[1]));
}

// bf16 split helpers: hi = truncate-to-bf16 (top 16 bits), lo = residual.
__device__ __forceinline__ float hi_part(float x) {
    return __uint_as_float(__float_as_uint(x) & 0xffff0000u);
}
__device__ __forceinline__ uint32_t pack_hi(float x0, float x1) {
    uint32_t u0 = __float_as_uint(x0), u1 = __float_as_uint(x1);
    return (u1 & 0xffff0000u) | (u0 >> 16);
}

// ---------------- mma.sync tf32 GEMM (unchanged from round 12) ---------------
#define APITCH 36
#define BPITCH 136
#define GEMM_SMEM ((2 * 128 * APITCH + 2 * 32 * BPITCH) * 4)   // 71680 B

__global__ __launch_bounds__(256, 2) void gemm_mma(
    const float* __restrict__ A, const float* __restrict__ W,
    const float* __restrict__ bias, float* __restrict__ C) {
    extern __shared__ float gsm[];
    float* sA = gsm;
    float* sB = gsm + 2 * 128 * APITCH;

    const int tid = threadIdx.x;
    const int lane = tid & 31;
    const int wid = tid >> 5;
    const int g = lane >> 2;
    const int tg = lane & 3;
    const int wm = wid & 1;
    const int wn = wid >> 1;
    const int m0 = blockIdx.y * 128;
    const int n0 = blockIdx.x * 128;

    const int lrowA = tid >> 3;
    const int lc4A = (tid & 7) * 4;
    const int lrowB = tid >> 5;
    const int lc4B = (tid & 31) * 4;

    const float* Ag = A + (size_t)(m0 + lrowA) * 1024 + lc4A;
    const float* Wg = W + (size_t)lrowB * 1024 + n0 + lc4B;
    const uint32_t sBu = smem_u32(sB);

    float acc[4][4][4] = {};
    float4 ra[4];

#pragma unroll
    for (int j = 0; j < 4; j++)
        ra[j] = *(const float4*)(Ag + (size_t)j * 32 * 1024);
#pragma unroll
    for (int j = 0; j < 4; j++)
        CP_ASYNC16(sBu + (uint32_t)(((lrowB + j * 8) * BPITCH + lc4B) * 4),
                   Wg + (size_t)j * 8 * 1024);
    CP_COMMIT();

    for (int it = 0; it < 32; ++it) {
        {
            float* dA = sA + (it & 1) * 128 * APITCH;
#pragma unroll
            for (int j = 0; j < 4; j++) {
                uint4 ta = make_uint4(f2tf32(ra[j].x), f2tf32(ra[j].y),
                                      f2tf32(ra[j].z), f2tf32(ra[j].w));
                *(uint4*)&dA[(lrowA + j * 32) * APITCH + lc4A] = ta;
            }
        }
        if (it + 1 < 32) {
            const float* An = Ag + (size_t)(it + 1) * 32;
#pragma unroll
            for (int j = 0; j < 4; j++)
                ra[j] = *(const float4*)(An + (size_t)j * 32 * 1024);
            const float* Wn = Wg + (size_t)(it + 1) * 32 * 1024;
            const uint32_t sbn = sBu + ((it + 1) & 1) * 32 * BPITCH * 4;
#pragma unroll
            for (int j = 0; j < 4; j++)
                CP_ASYNC16(sbn + (uint32_t)(((lrowB + j * 8) * BPITCH + lc4B) * 4),
                           Wn + (size_t)j * 8 * 1024);
            CP_COMMIT();
            CP_WAIT(1);
        } else {
            CP_WAIT(0);
        }
        __syncthreads();

        {
            const uint32_t* cA = (const uint32_t*)(sA + (it & 1) * 128 * APITCH);
            const float* cB = sB + (it & 1) * 32 * BPITCH;
#pragma unroll
            for (int ks = 0; ks < 4; ks++) {
                const int kb = ks * 8;
                uint32_t af[4][4];
#pragma unroll
                for (int mt = 0; mt < 4; mt++) {
                    const int r = wm * 64 + mt * 16 + g;
                    af[mt][0] = cA[r * APITCH + kb + tg];
                    af[mt][1] = cA[(r + 8) * APITCH + kb + tg];
                    af[mt][2] = cA[r * APITCH + kb + tg + 4];
                    af[mt][3] = cA[(r + 8) * APITCH + kb + tg + 4];
                }
                uint32_t bf[4][2];
#pragma unroll
                for (int nt = 0; nt < 4; nt++) {
                    const int c = wn * 32 + nt * 8 + g;
                    bf[nt][0] = f2tf32(cB[(kb + tg) * BPITCH + c]);
                    bf[nt][1] = f2tf32(cB[(kb + tg + 4) * BPITCH + c]);
                }
#pragma unroll
                for (int mt = 0; mt < 4; mt++)
#pragma unroll
                    for (int nt = 0; nt < 4; nt++)
                        mma_tf32(acc[mt][nt], af[mt], bf[nt]);
            }
        }
        __syncthreads();
    }

#pragma unroll
    for (int mt = 0; mt < 4; mt++) {
        const int row = m0 + wm * 64 + mt * 16 + g;
#pragma unroll
        for (int nt = 0; nt < 4; nt++) {
            const int col = n0 + wn * 32 + nt * 8 + tg * 2;
            const float2 bv = *(const float2*)&bias[col];
            float2 o0, o1;
            o0.x = acc[mt][nt][0] + bv.x;
            o0.y = acc[mt][nt][1] + bv.y;
            o1.x = acc[mt][nt][2] + bv.x;
            o1.y = acc[mt][nt][3] + bv.y;
            *(float2*)(C + (size_t)row * 1024 + col) = o0;
            *(float2*)(C + (size_t)(row + 8) * 1024 + col) = o1;
        }
    }
}

// ---------------- Flash attention: warp-row ownership, P in registers --------
// CTA: 128 queries, 64 keys/iter, 8 warps; warp w owns rows w*16..w*16+15,
// full key/d range. QK accumulators re-used directly as PV A-operands.
// Softmax entirely warp-local (quad shuffles); m/l are per-thread registers.
// smem (u32): Qh/Ql[128][36], Kh/Kl[64][36], Vh/Vl[64][36] = 73,728 B.
#define AQH 0
#define AQL 4608
#define AKH 9216
#define AKL 11520
#define AVH 13824
#define AVL 16128
#define ATTN_SMEM (18432 * 4)

__global__ __launch_bounds__(256, 2) void attn_mma(
    const float* __restrict__ Q, const float* __restrict__ K,
    const float* __restrict__ V, float* __restrict__ O) {
    extern __shared__ uint32_t smu[];
    uint32_t* Qh = smu + AQH;
    uint32_t* Ql = smu + AQL;
    uint32_t* Kh = smu + AKH;
    uint32_t* Kl = smu + AKL;
    uint32_t* Vh = smu + AVH;
    uint32_t* Vl = smu + AVL;

    const int tid = threadIdx.x;
    const int lane = tid & 31;
    const int wid = tid >> 5;     // warp owns query rows wid*16 .. wid*16+15
    const int g = lane >> 2;
    const int tg = lane & 3;
    const int bh = blockIdx.y;
    const int b = bh >> 4;
    const int h = bh & 15;
    const int q0 = blockIdx.x * 128;

    const float* Qg = Q + (size_t)(b * L_SEQ + q0) * E_DIM + h * D_HEAD;
    const float* Kg0 = K + (size_t)b * S_SEQ * E_DIM + h * D_HEAD;
    const float* Vg0 = V + (size_t)b * S_SEQ * E_DIM + h * D_HEAD;

    // Q: pre-scale by (1/8)*log2(e), split bf16 hi/lo, pack d-pairs.
    const float QSCALE = 0.125f * 1.4426950408889634f;
#pragma unroll
    for (int p = 0; p < 16; p++) {
        int idx = tid + p * 256;
        int r = idx >> 5;
        int dp = idx & 31;
        float2 q = *(const float2*)(Qg + (size_t)r * E_DIM + 2 * dp);
        float x0 = q.x * QSCALE, x1 = q.y * QSCALE;
        Qh[r * 36 + dp] = pack_hi(x0, x1);
        Ql[r * 36 + dp] = pack_hi(x0 - hi_part(x0), x1 - hi_part(x1));
    }

    // per-thread softmax state for rows (wid*16+g) and (wid*16+g+8)
    float m0 = -1e30f, m1 = -1e30f, l0 = 0.0f, l1 = 0.0f;
    float oacc[8][4] = {};   // 8 d-tiles of n8 each

    for (int t = 0; t < S_SEQ / 64; ++t) {
        const float* Kg = Kg0 + (size_t)t * 64 * E_DIM;
        const float* Vg = Vg0 + (size_t)t * 64 * E_DIM;
#pragma unroll
        for (int p = 0; p < 8; p++) {
            int idx = tid + p * 256;
            int j = idx >> 5;
            int dp = idx & 31;
            float2 kv = *(const float2*)(Kg + (size_t)j * E_DIM + 2 * dp);
            Kh[j * 36 + dp] = pack_hi(kv.x, kv.y);
            Kl[j * 36 + dp] = pack_hi(kv.x - hi_part(kv.x), kv.y - hi_part(kv.y));
        }
#pragma unroll
        for (int p = 0; p < 8; p++) {
            int idx = tid + p * 256;
            int d = idx & 63;
            int jp = idx >> 6;
            float v0 = Vg[(size_t)(2 * jp) * E_DIM + d];
            float v1 = Vg[(size_t)(2 * jp + 1) * E_DIM + d];
            Vh[d * 36 + jp] = pack_hi(v0, v1);
            Vl[d * 36 + jp] = pack_hi(v0 - hi_part(v0), v1 - hi_part(v1));
        }
        __syncthreads();   // K/V tiles ready

        // ---- QK^T: warp computes 16x64 scores, sc[nt] = n-tile (keys nt*8..)
        float sc[8][4] = {};
#pragma unroll
        for (int ks = 0; ks < 4; ks++) {
            int r0 = (wid * 16 + g) * 36 + ks * 8 + tg;
            uint32_t ah[4], al[4];
            ah[0] = Qh[r0];     ah[1] = Qh[r0 + 288];
            ah[2] = Qh[r0 + 4]; ah[3] = Qh[r0 + 292];
            al[0] = Ql[r0];     al[1] = Ql[r0 + 288];
            al[2] = Ql[r0 + 4]; al[3] = Ql[r0 + 292];
#pragma unroll
            for (int nt = 0; nt < 8; nt++) {
                int jb = (nt * 8 + g) * 36 + ks * 8 + tg;
                uint32_t bh2[2], bl2[2];
                bh2[0] = Kh[jb]; bh2[1] = Kh[jb + 4];
                bl2[0] = Kl[jb]; bl2[1] = Kl[jb + 4];
                mma_bf16(sc[nt], ah, bh2);
                mma_bf16(sc[nt], al, bh2);
                mma_bf16(sc[nt], ah, bl2);
            }
        }

        // ---- warp-local row max (rows g and g+8)
        float mx0 = -1e30f, mx1 = -1e30f;
#pragma unroll
        for (int nt = 0; nt < 8; nt++) {
            mx0 = fmaxf(mx0, fmaxf(sc[nt][0], sc[nt][1]));
            mx1 = fmaxf(mx1, fmaxf(sc[nt][2], sc[nt][3]));
        }
        mx0 = fmaxf(mx0, __shfl_xor_sync(0xffffffffu, mx0, 1));
        mx0 = fmaxf(mx0, __shfl_xor_sync(0xffffffffu, mx0, 2));
        mx1 = fmaxf(mx1, __shfl_xor_sync(0xffffffffu, mx1, 1));
        mx1 = fmaxf(mx1, __shfl_xor_sync(0xffffffffu, mx1, 2));
        float mn0 = fmaxf(m0, mx0);
        float mn1 = fmaxf(m1, mx1);
        float a0 = exp2f(m0 - mn0);
        float a1 = exp2f(m1 - mn1);

        // rescale O accumulators
#pragma unroll
        for (int nt = 0; nt < 8; nt++) {
            oacc[nt][0] *= a0; oacc[nt][1] *= a0;
            oacc[nt][2] *= a1; oacc[nt][3] *= a1;
        }

        // ---- exp2 + pack P hi/lo directly into PV A-fragments (registers)
        uint32_t phg[8], phh[8], plg[8], plh[8];
        float ls0 = 0.0f, ls1 = 0.0f;
#pragma unroll
        for (int nt = 0; nt < 8; nt++) {
            float e0 = exp2f(sc[nt][0] - mn0);
            float e1 = exp2f(sc[nt][1] - mn0);
            float e2 = exp2f(sc[nt][2] - mn1);
            float e3 = exp2f(sc[nt][3] - mn1);
            ls0 += e0 + e1;
            ls1 += e2 + e3;
            phg[nt] = pack_hi(e0, e1);
            plg[nt] = pack_hi(e0 - hi_part(e0), e1 - hi_part(e1));
            phh[nt] = pack_hi(e2, e3);
            plh[nt] = pack_hi(e2 - hi_part(e2), e3 - hi_part(e3));
        }
        ls0 += __shfl_xor_sync(0xffffffffu, ls0, 1);
        ls0 += __shfl_xor_sync(0xffffffffu, ls0, 2);
        ls1 += __shfl_xor_sync(0xffffffffu, ls1, 1);
        ls1 += __shfl_xor_sync(0xffffffffu, ls1, 2);
        l0 = l0 * a0 + ls0;
        l1 = l1 * a1 + ls1;
        m0 = mn0;
        m1 = mn1;

        // ---- O += P @ V  (P fragments straight from registers)
#pragma unroll
        for (int ks = 0; ks < 4; ks++) {
            uint32_t pah[4], pal[4];
            pah[0] = phg[2 * ks];     pah[1] = phh[2 * ks];
            pah[2] = phg[2 * ks + 1]; pah[3] = phh[2 * ks + 1];
            pal[0] = plg[2 * ks];     pal[1] = plh[2 * ks];
            pal[2] = plg[2 * ks + 1]; pal[3] = plh[2 * ks + 1];
#pragma unroll
            for (int nt = 0; nt < 8; nt++) {
                int db = (nt * 8 + g) * 36 + ks * 8 + tg;
                uint32_t vbh[2], vbl[2];
                vbh[0] = Vh[db]; vbh[1] = Vh[db + 4];
                vbl[0] = Vl[db]; vbl[1] = Vl[db + 4];
                mma_bf16(oacc[nt], pah, vbh);
                mma_bf16(oacc[nt], pal, vbh);
                mma_bf16(oacc[nt], pah, vbl);
            }
        }
        __syncthreads();   // protect K/V tiles before next load
    }

    // ---- finalize: divide by l, write [B,L,E]
    {
        float* Og = O + (size_t)(b * L_SEQ + q0) * E_DIM + h * D_HEAD;
        const int r = wid * 16 + g;
        float i0 = 1.0f / l0;
        float i1 = 1.0f / l1;
#pragma unroll
        for (int nt = 0; nt < 8; nt++) {
            int c = nt * 8 + 2 * tg;
            *(float2*)(Og + (size_t)r * E_DIM + c) =
                make_float2(oacc[nt][0] * i0, oacc[nt][1] * i0);
            *(float2*)(Og + (size_t)(r + 8) * E_DIM + c) =
                make_float2(oacc[nt][2] * i1, oacc[nt][3] * i1);
        }
    }
}

// ---------------- launch -----------------------------------------------------
extern "C" void kernel_launch(void* const* d_in, const int* in_sizes, int n_in,
                              void* d_out, int out_size) {
    (void)in_sizes; (void)n_in; (void)out_size;
    const float* x   = (const float*)d_in[0];
    const float* ctx = (const float*)d_in[1];
    const float* Wq  = (const float*)d_in[2];
    const float* bq  = (const float*)d_in[3];
    const float* Wk  = (const float*)d_in[4];
    const float* bk  = (const float*)d_in[5];
    const float* Wv  = (const float*)d_in[6];
    const float* bv  = (const float*)d_in[7];
    const float* Wp  = (const float*)d_in[8];
    const float* bp  = (const float*)d_in[9];
    float* out = (float*)d_out;

    float *pQ, *pK, *pV, *pAO;
    cudaGetSymbolAddress((void**)&pQ, g_Q);
    cudaGetSymbolAddress((void**)&pK, g_K);
    cudaGetSymbolAddress((void**)&pV, g_V);
    cudaGetSymbolAddress((void**)&pAO, g_AO);

    cudaFuncSetAttribute(gemm_mma, cudaFuncAttributeMaxDynamicSharedMemorySize,
                         GEMM_SMEM);
    cudaFuncSetAttribute(attn_mma, cudaFuncAttributeMaxDynamicSharedMemorySize,
                         ATTN_SMEM);

    dim3 gGemm(E_DIM / 128, M_ROWS / 128);   // (8, 32)
    gemm_mma<<<gGemm, 256, GEMM_SMEM>>>(x,   Wq, bq, pQ);
    gemm_mma<<<gGemm, 256, GEMM_SMEM>>>(ctx, Wk, bk, pK);
    gemm_mma<<<gGemm, 256, GEMM_SMEM>>>(ctx, Wv, bv, pV);

    dim3 gAttn(L_SEQ / 128, B_SZ * H_NUM);   // (16, 32)
    attn_mma<<<gAttn, 256, ATTN_SMEM>>>(pQ, pK, pV, pAO);

    gemm_mma<<<gGemm, 256, GEMM_SMEM>>>(pAO, Wp, bp, out);
}